// round 14
// baseline (speedup 1.0000x reference)
#include <cuda_runtime.h>
#include <math.h>
#include <stdint.h>

#define NN   50000
#define NE   800000
#define IND  256
#define HID  128
#define OUTD 64
#define NB   4096
#define BN_EPS 1e-5f
#define SLOPE  0.01f

#define SCAN_BLK  1024
#define NSCANBLK  ((NN + SCAN_BLK - 1) / SCAN_BLK)   // 49

// ---------------- scratch (device globals; no allocation allowed) ----------
__device__ int   g_degi[NN];                      // int degree (no self loop)
__device__ int   g_off [NN];                      // local (per-scan-block) offsets
__device__ int   g_base[NSCANBLK];                // scan-block bases
__device__ int   g_bsum[NSCANBLK];                // scan-block sums
__device__ int   g_cnt [NN];                      // scatter counters
__device__ int   g_ssrc[NE];                      // src ids sorted by dst
__device__ float g_s   [(size_t)NN * HID];        // dinv-scaled linear output (fp32)
__device__ float g_accL[3][(size_t)NN * HID];     // per-layer pre-BN activations
__device__ float g_stats[3][2 * HID];             // per-layer column sum / sumsq

// ---------------- bf16 helpers ------------------------------------------------
__device__ __forceinline__ uint32_t bf16pair(float f0, float f1) {
    uint32_t r;
    asm("cvt.rn.bf16x2.f32 %0, %1, %2;" : "=r"(r) : "f"(f1), "f"(f0));
    return r;
}
__device__ __forceinline__ float bf_lo(uint32_t p) { return __uint_as_float(p << 16); }
__device__ __forceinline__ float bf_hi(uint32_t p) { return __uint_as_float(p & 0xffff0000u); }

// m16n8k16 row.col bf16 MMA, fp32 accumulate
__device__ __forceinline__ void mma16816(float* c, const uint32_t* a, const uint32_t* b) {
    asm volatile(
        "mma.sync.aligned.m16n8k16.row.col.f32.bf16.bf16.f32 "
        "{%0,%1,%2,%3}, {%4,%5,%6,%7}, {%8,%9}, {%0,%1,%2,%3};"
        : "+f"(c[0]), "+f"(c[1]), "+f"(c[2]), "+f"(c[3])
        : "r"(a[0]), "r"(a[1]), "r"(a[2]), "r"(a[3]), "r"(b[0]), "r"(b[1]));
}

// ---------------- degree / CSR -------------------------------------------------
__global__ void k_deg_count(const int* __restrict__ dst) {
    int e = blockIdx.x * blockDim.x + threadIdx.x;
    if (e < NE) atomicAdd(&g_degi[dst[e]], 1);
}

// Parallel ordered scan, stage 1: per-block inclusive scan (1024 wide).
// Writes exclusive local offsets to g_off and block sums to g_bsum.
__global__ void k_scan1() {
    __shared__ int sc[SCAN_BLK];
    int t = threadIdx.x;
    int i = blockIdx.x * SCAN_BLK + t;
    int d = (i < NN) ? g_degi[i] : 0;
    sc[t] = d;
    __syncthreads();
    #pragma unroll
    for (int s = 1; s < SCAN_BLK; s <<= 1) {
        int v = (t >= s) ? sc[t - s] : 0;
        __syncthreads();
        sc[t] += v;
        __syncthreads();
    }
    if (i < NN) g_off[i] = sc[t] - d;
    if (t == SCAN_BLK - 1) g_bsum[blockIdx.x] = sc[t];
}

// Stage 2: exclusive scan of the 49 block sums (one small block).
__global__ void k_scan2() {
    __shared__ int sc[64];
    int t = threadIdx.x;           // 64 threads
    int v = (t < NSCANBLK) ? g_bsum[t] : 0;
    sc[t] = v;
    __syncthreads();
    #pragma unroll
    for (int s = 1; s < 64; s <<= 1) {
        int u = (t >= s) ? sc[t - s] : 0;
        __syncthreads();
        sc[t] += u;
        __syncthreads();
    }
    if (t < NSCANBLK) g_base[t] = sc[t] - v;   // exclusive
}

// ---------------- tensor GEMM (split-bf16, mma.sync) --------------------------
// D = Ahi*Bhi + Ahi*Blo + Alo*Bhi ; fp32 accum.
// CTA 128x128, 8 warps (4m x 2n), warp tile 32x64. K chunked at 64.
#define TCH    64
#define TSTR   72
#define TILE_E (128 * TSTR)
#define MM_AHI 0
#define MM_ALO (TILE_E)
#define MM_BHI (2 * TILE_E)
#define MM_BLO (3 * TILE_E)
#define MM_SC  (4 * TILE_E * 2)
#define MM_SMEM (4 * TILE_E * 2 + 2 * HID * 4)

#define GEMM_BLOCKS ((NN + 127) / 128)          // 391
#define SCAT_BLOCKS ((NE + 255) / 256)          // 3125

template <int K, bool BN>
__device__ __forceinline__ void gemm_body(
    int blk,
    const float* __restrict__ X, const float* __restrict__ W,
    const float* __restrict__ stats, const float* __restrict__ gamma,
    const float* __restrict__ beta) {
    extern __shared__ char smc[];
    uint16_t* TB     = (uint16_t*)smc;
    float*    sScale = (float*)(smc + MM_SC);
    float*    sShift = sScale + HID;

    const int t    = threadIdx.x;
    const int wid  = t >> 5;
    const int lane = t & 31;
    const int gid  = lane >> 2;
    const int tig  = lane & 3;
    const int m0   = blk * 128;
    const int wm   = wid & 3;
    const int wn   = wid >> 2;

    if (BN && t < HID) {
        float mean = stats[t] * (1.0f / NN);
        float var  = stats[HID + t] * (1.0f / NN) - mean * mean;
        float sc   = gamma[t] * rsqrtf(var + BN_EPS);
        sScale[t] = sc;
        sShift[t] = beta[t] - mean * sc;
    }
    if (BN) __syncthreads();

    float acc[2][8][4];
    #pragma unroll
    for (int mi = 0; mi < 2; mi++)
        #pragma unroll
        for (int ni = 0; ni < 8; ni++)
            #pragma unroll
            for (int j = 0; j < 4; j++) acc[mi][ni][j] = 0.0f;

    const int NCH = K / TCH;
    for (int kc = 0; kc < NCH; kc++) {
        #pragma unroll
        for (int j = 0; j < 8; j++) {
            int idx = j * 256 + t;
            int row = idx >> 4;
            int c4  = (idx & 15) * 4;
            int m   = m0 + row;
            float4 v = (m < NN)
                ? *(const float4*)(X + (size_t)m * K + kc * TCH + c4)
                : make_float4(0.f, 0.f, 0.f, 0.f);
            if (BN) {
                int kg = kc * TCH + c4;
                v.x = v.x * sScale[kg + 0] + sShift[kg + 0];
                v.y = v.y * sScale[kg + 1] + sShift[kg + 1];
                v.z = v.z * sScale[kg + 2] + sShift[kg + 2];
                v.w = v.w * sScale[kg + 3] + sShift[kg + 3];
            }
            uint32_t hp0 = bf16pair(v.x, v.y);
            uint32_t hp1 = bf16pair(v.z, v.w);
            uint32_t lp0 = bf16pair(v.x - bf_lo(hp0), v.y - bf_hi(hp0));
            uint32_t lp1 = bf16pair(v.z - bf_lo(hp1), v.w - bf_hi(hp1));
            int eo = row * TSTR + c4;
            *(uint2*)(TB + MM_AHI + eo) = make_uint2(hp0, hp1);
            *(uint2*)(TB + MM_ALO + eo) = make_uint2(lp0, lp1);

            float4 w = *(const float4*)(W + (size_t)row * K + kc * TCH + c4);
            uint32_t whp0 = bf16pair(w.x, w.y);
            uint32_t whp1 = bf16pair(w.z, w.w);
            uint32_t wlp0 = bf16pair(w.x - bf_lo(whp0), w.y - bf_hi(whp0));
            uint32_t wlp1 = bf16pair(w.z - bf_lo(whp1), w.w - bf_hi(whp1));
            *(uint2*)(TB + MM_BHI + eo) = make_uint2(whp0, whp1);
            *(uint2*)(TB + MM_BLO + eo) = make_uint2(wlp0, wlp1);
        }
        __syncthreads();

        #pragma unroll
        for (int ks = 0; ks < 4; ks++) {
            const int kb = ks * 16 + 2 * tig;
            uint32_t ahi[2][4], alo[2][4];
            #pragma unroll
            for (int mi = 0; mi < 2; mi++) {
                int r = wm * 32 + mi * 16 + gid;
                ahi[mi][0] = *(const uint32_t*)(TB + MM_AHI + r * TSTR + kb);
                ahi[mi][1] = *(const uint32_t*)(TB + MM_AHI + (r + 8) * TSTR + kb);
                ahi[mi][2] = *(const uint32_t*)(TB + MM_AHI + r * TSTR + kb + 8);
                ahi[mi][3] = *(const uint32_t*)(TB + MM_AHI + (r + 8) * TSTR + kb + 8);
                alo[mi][0] = *(const uint32_t*)(TB + MM_ALO + r * TSTR + kb);
                alo[mi][1] = *(const uint32_t*)(TB + MM_ALO + (r + 8) * TSTR + kb);
                alo[mi][2] = *(const uint32_t*)(TB + MM_ALO + r * TSTR + kb + 8);
                alo[mi][3] = *(const uint32_t*)(TB + MM_ALO + (r + 8) * TSTR + kb + 8);
            }
            #pragma unroll
            for (int ni = 0; ni < 8; ni++) {
                int n = wn * 64 + ni * 8 + gid;
                uint32_t bh[2], bl[2];
                bh[0] = *(const uint32_t*)(TB + MM_BHI + n * TSTR + kb);
                bh[1] = *(const uint32_t*)(TB + MM_BHI + n * TSTR + kb + 8);
                bl[0] = *(const uint32_t*)(TB + MM_BLO + n * TSTR + kb);
                bl[1] = *(const uint32_t*)(TB + MM_BLO + n * TSTR + kb + 8);
                mma16816(acc[0][ni], ahi[0], bh);
                mma16816(acc[1][ni], ahi[1], bh);
                mma16816(acc[0][ni], alo[0], bh);
                mma16816(acc[1][ni], alo[1], bh);
                mma16816(acc[0][ni], ahi[0], bl);
                mma16816(acc[1][ni], ahi[1], bl);
            }
        }
        __syncthreads();
    }

    // epilogue: scale rows by dinv, store fp32
    #pragma unroll
    for (int mi = 0; mi < 2; mi++) {
        int r0 = m0 + wm * 32 + mi * 16 + gid;
        int r1 = r0 + 8;
        float d0 = (r0 < NN) ? rsqrtf(1.0f + (float)g_degi[r0]) : 0.0f;
        float d1 = (r1 < NN) ? rsqrtf(1.0f + (float)g_degi[r1]) : 0.0f;
        #pragma unroll
        for (int ni = 0; ni < 8; ni++) {
            int col = wn * 64 + ni * 8 + 2 * tig;
            if (r0 < NN)
                *(float2*)(g_s + (size_t)r0 * HID + col) =
                    make_float2(acc[mi][ni][0] * d0, acc[mi][ni][1] * d0);
            if (r1 < NN)
                *(float2*)(g_s + (size_t)r1 * HID + col) =
                    make_float2(acc[mi][ni][2] * d1, acc[mi][ni][3] * d1);
        }
    }
}

// plain GEMM kernel (layers 1, 2)
template <int K, bool BN>
__global__ void __launch_bounds__(256, 2)
k_gemm(const float* __restrict__ X, const float* __restrict__ W,
       const float* __restrict__ stats, const float* __restrict__ gamma,
       const float* __restrict__ beta) {
    gemm_body<K, BN>(blockIdx.x, X, W, stats, gamma, beta);
}

// fused layer-0 GEMM + CSR scatter (independent work, one launch).
__global__ void __launch_bounds__(256, 2)
k_gemm0_scatter(const float* __restrict__ X, const float* __restrict__ W,
                const int* __restrict__ src, const int* __restrict__ dst) {
    if (blockIdx.x >= GEMM_BLOCKS) {
        int e = (blockIdx.x - GEMM_BLOCKS) * 256 + threadIdx.x;
        if (e < NE) {
            int d = dst[e];
            int p = g_base[d >> 10] + g_off[d] + atomicAdd(&g_cnt[d], 1);
            g_ssrc[p] = src[e];
        }
        return;
    }
    gemm_body<IND, false>(blockIdx.x, X, W, nullptr, nullptr, nullptr);
}

// ---------------- fused CSR aggregation + bias/ReLU + stats ------------------
__global__ void __launch_bounds__(256)
k_agg(const float* __restrict__ bias, float* __restrict__ outv,
      float* __restrict__ stats) {
    __shared__ float sSum[HID], sSq[HID];
    int t = threadIdx.x;
    if (t < HID) { sSum[t] = 0.0f; sSq[t] = 0.0f; }
    __syncthreads();

    int gw   = (blockIdx.x * 256 + t) >> 5;        // node id
    int lane = t & 31;
    int beg = g_base[gw >> 10] + g_off[gw];
    int end = beg + g_degi[gw];
    const float4* S = (const float4*)g_s;
    float4 acc = S[(size_t)gw * 32 + lane];        // self-loop
    int e = beg;
    for (; e + 4 <= end; e += 4) {
        int u0 = g_ssrc[e], u1 = g_ssrc[e + 1], u2 = g_ssrc[e + 2], u3 = g_ssrc[e + 3];
        float4 v0 = S[(size_t)u0 * 32 + lane];
        float4 v1 = S[(size_t)u1 * 32 + lane];
        float4 v2 = S[(size_t)u2 * 32 + lane];
        float4 v3 = S[(size_t)u3 * 32 + lane];
        acc.x += (v0.x + v1.x) + (v2.x + v3.x);
        acc.y += (v0.y + v1.y) + (v2.y + v3.y);
        acc.z += (v0.z + v1.z) + (v2.z + v3.z);
        acc.w += (v0.w + v1.w) + (v2.w + v3.w);
    }
    for (; e < end; e++) {
        int u = g_ssrc[e];
        float4 v = S[(size_t)u * 32 + lane];
        acc.x += v.x; acc.y += v.y; acc.z += v.z; acc.w += v.w;
    }

    float dinv = rsqrtf(1.0f + (float)g_degi[gw]);
    float4 b4 = ((const float4*)bias)[lane];
    float4 v;
    v.x = fmaxf(acc.x * dinv + b4.x, 0.0f);
    v.y = fmaxf(acc.y * dinv + b4.y, 0.0f);
    v.z = fmaxf(acc.z * dinv + b4.z, 0.0f);
    v.w = fmaxf(acc.w * dinv + b4.w, 0.0f);
    ((float4*)outv)[(size_t)gw * 32 + lane] = v;

    int c = lane * 4;
    atomicAdd(&sSum[c + 0], v.x);     atomicAdd(&sSq[c + 0], v.x * v.x);
    atomicAdd(&sSum[c + 1], v.y);     atomicAdd(&sSq[c + 1], v.y * v.y);
    atomicAdd(&sSum[c + 2], v.z);     atomicAdd(&sSq[c + 2], v.z * v.z);
    atomicAdd(&sSum[c + 3], v.w);     atomicAdd(&sSq[c + 3], v.w * v.w);
    __syncthreads();

    if (t < 32) {
        float4 s = *(const float4*)&sSum[t * 4];
        atomicAdd((float4*)&stats[t * 4], s);
    } else if (t < 64) {
        int j = t - 32;
        float4 s = *(const float4*)&sSq[j * 4];
        atomicAdd((float4*)&stats[HID + j * 4], s);
    }
}

// ---------------- attention pooling + projection, 32 rows per block ---------
#define SM_W   0
#define SM_E   (SM_W + 128*132)
#define SM_P   (SM_E + 3*128*36)
#define SM_OW  (SM_P + 128*36)
#define SM_ES  (SM_OW + 128*66)
#define SM_AL  (SM_ES + 96)
#define SM_SC  (SM_AL + 96)
#define SM_SH  (SM_SC + 3*128)
#define SM_FLOATS (SM_SH + 3*128)

__global__ void k_att(const int* __restrict__ dp, const int* __restrict__ tp,
                      const int* __restrict__ dn, const int* __restrict__ tn,
                      const float* __restrict__ WD, const float* __restrict__ WT,
                      const float* __restrict__ qD, const float* __restrict__ qT,
                      const float* __restrict__ ow, const float* __restrict__ ob,
                      const float* __restrict__ gamma, const float* __restrict__ beta,
                      float* __restrict__ out) {
    extern __shared__ float sm[];
    __shared__ int s_node[32];

    const int tid = threadIdx.x;           // 256
    const int blk = blockIdx.x;            // 512
    const int grp = blk >> 7;
    const int jb  = (blk & 127) * 32;

    const int*   ids = (grp == 0) ? dp : (grp == 1) ? tp : (grp == 2) ? dn : tn;
    const float* W   = (grp & 1) ? WT : WD;
    const float* q   = (grp & 1) ? qT : qD;

    if (tid < 32) s_node[tid] = ids[jb + tid];
    if (tid < 96) sm[SM_ES + tid] = 0.0f;
    if (tid < 128) {
        #pragma unroll
        for (int l = 0; l < 3; l++) {
            const float* st = g_stats[l];
            float mean = st[tid] * (1.0f / NN);
            float var  = st[HID + tid] * (1.0f / NN) - mean * mean;
            float sc   = gamma[tid] * rsqrtf(var + BN_EPS);
            sm[SM_SC + l * 128 + tid] = sc;
            sm[SM_SH + l * 128 + tid] = beta[tid] - mean * sc;
        }
    }
    __syncthreads();

    #pragma unroll
    for (int i = 0; i < 64; i++) {
        int idx = i * 256 + tid;
        int t = idx >> 7, k = idx & 127;
        sm[SM_W + k * 132 + t] = W[idx];
    }
    #pragma unroll
    for (int i = 0; i < 32; i++) {
        int idx = i * 256 + tid;
        int o = idx >> 7, k = idx & 127;
        sm[SM_OW + k * 66 + o] = ow[idx];
    }
    #pragma unroll
    for (int l = 0; l < 3; l++)
        #pragma unroll
        for (int i = 0; i < 16; i++) {
            int idx = i * 256 + tid;
            int r = idx >> 7, k = idx & 127;
            float raw = g_accL[l][(size_t)s_node[r] * HID + k];
            sm[SM_E + ((l * 128 + k) * 36) + r] =
                raw * sm[SM_SC + l * 128 + k] + sm[SM_SH + l * 128 + k];
        }
    __syncthreads();

    const int tr = tid & 7;
    const int tt = tid >> 3;
    const int r0 = tr * 4;
    const int t0 = tt * 4;

    float ql0 = q[t0], ql1 = q[t0 + 1], ql2 = q[t0 + 2], ql3 = q[t0 + 3];

    for (int l = 0; l < 3; l++) {
        float acc[4][4];
        #pragma unroll
        for (int i = 0; i < 4; i++)
            #pragma unroll
            for (int j = 0; j < 4; j++) acc[i][j] = 0.0f;

        const float* eb = sm + SM_E + (l * 128) * 36;
        #pragma unroll 4
        for (int k = 0; k < 128; k++) {
            float4 a = *(const float4*)(eb + k * 36 + r0);
            float4 b = *(const float4*)(sm + SM_W + k * 132 + t0);
            acc[0][0] += a.x * b.x; acc[0][1] += a.x * b.y; acc[0][2] += a.x * b.z; acc[0][3] += a.x * b.w;
            acc[1][0] += a.y * b.x; acc[1][1] += a.y * b.y; acc[1][2] += a.y * b.z; acc[1][3] += a.y * b.w;
            acc[2][0] += a.z * b.x; acc[2][1] += a.z * b.y; acc[2][2] += a.z * b.z; acc[2][3] += a.z * b.w;
            acc[3][0] += a.w * b.x; acc[3][1] += a.w * b.y; acc[3][2] += a.w * b.z; acc[3][3] += a.w * b.w;
        }
        #pragma unroll
        for (int i = 0; i < 4; i++) {
            float h0 = acc[i][0], h1 = acc[i][1], h2 = acc[i][2], h3 = acc[i][3];
            h0 = (h0 > 0.0f) ? h0 : SLOPE * h0;
            h1 = (h1 > 0.0f) ? h1 : SLOPE * h1;
            h2 = (h2 > 0.0f) ? h2 : SLOPE * h2;
            h3 = (h3 > 0.0f) ? h3 : SLOPE * h3;
            float pe = h0 * ql0 + h1 * ql1 + h2 * ql2 + h3 * ql3;
            atomicAdd(&sm[SM_ES + l * 32 + r0 + i], pe);
        }
    }
    __syncthreads();

    if (tid < 32) {
        float e0 = sm[SM_ES + tid], e1 = sm[SM_ES + 32 + tid], e2 = sm[SM_ES + 64 + tid];
        float m  = fmaxf(e0, fmaxf(e1, e2));
        float a0 = expf(e0 - m), a1 = expf(e1 - m), a2 = expf(e2 - m);
        float s  = 1.0f / (a0 + a1 + a2);
        sm[SM_AL + tid]      = a0 * s;
        sm[SM_AL + 32 + tid] = a1 * s;
        sm[SM_AL + 64 + tid] = a2 * s;
    }
    __syncthreads();

    #pragma unroll
    for (int i = 0; i < 16; i++) {
        int idx = i * 256 + tid;
        int k = idx >> 5, r = idx & 31;
        float v = sm[SM_AL + r]      * sm[SM_E + (0 * 128 + k) * 36 + r]
                + sm[SM_AL + 32 + r] * sm[SM_E + (1 * 128 + k) * 36 + r]
                + sm[SM_AL + 64 + r] * sm[SM_E + (2 * 128 + k) * 36 + r];
        sm[SM_P + k * 36 + r] = v;
    }
    __syncthreads();

    {
        const int o0 = tt * 2;
        float a0 = 0, a1 = 0, b0 = 0, b1 = 0, c0 = 0, c1 = 0, d0 = 0, d1 = 0;
        #pragma unroll 4
        for (int k = 0; k < 128; k++) {
            float4 p = *(const float4*)(sm + SM_P + k * 36 + r0);
            float2 w2 = *(const float2*)(sm + SM_OW + k * 66 + o0);
            a0 += p.x * w2.x; a1 += p.x * w2.y;
            b0 += p.y * w2.x; b1 += p.y * w2.y;
            c0 += p.z * w2.x; c1 += p.z * w2.y;
            d0 += p.w * w2.x; d1 += p.w * w2.y;
        }
        float ob0 = ob[o0], ob1 = ob[o0 + 1];
        int row = blk * 32 + r0;
        out[(size_t)(row + 0) * OUTD + o0]     = a0 + ob0;
        out[(size_t)(row + 0) * OUTD + o0 + 1] = a1 + ob1;
        out[(size_t)(row + 1) * OUTD + o0]     = b0 + ob0;
        out[(size_t)(row + 1) * OUTD + o0 + 1] = b1 + ob1;
        out[(size_t)(row + 2) * OUTD + o0]     = c0 + ob0;
        out[(size_t)(row + 2) * OUTD + o0 + 1] = c1 + ob1;
        out[(size_t)(row + 3) * OUTD + o0]     = d0 + ob0;
        out[(size_t)(row + 3) * OUTD + o0 + 1] = d1 + ob1;
    }
}

// ---------------- launch -----------------------------------------------------
extern "C" void kernel_launch(void* const* d_in, const int* in_sizes, int n_in,
                              void* d_out, int out_size) {
    const float* x     = (const float*)d_in[0];
    const int*   ei    = (const int*)  d_in[1];
    const int*   dp    = (const int*)  d_in[2];
    const int*   tp    = (const int*)  d_in[3];
    const int*   dn    = (const int*)  d_in[4];
    const int*   tn    = (const int*)  d_in[5];
    const float* w0    = (const float*)d_in[7];
    const float* b0    = (const float*)d_in[8];
    const float* w1    = (const float*)d_in[9];
    const float* b1    = (const float*)d_in[10];
    const float* w2    = (const float*)d_in[11];
    const float* b2    = (const float*)d_in[12];
    const float* gamma = (const float*)d_in[13];
    const float* beta  = (const float*)d_in[14];
    const float* WD    = (const float*)d_in[15];
    const float* WT    = (const float*)d_in[16];
    const float* qD    = (const float*)d_in[17];
    const float* qT    = (const float*)d_in[18];
    const float* ow    = (const float*)d_in[19];
    const float* ob    = (const float*)d_in[20];
    float*       out   = (float*)d_out;

    const int* src = ei;
    const int* dst = ei + NE;

    float* accBase = nullptr;
    cudaGetSymbolAddress((void**)&accBase, g_accL);
    float* statsBase = nullptr;
    cudaGetSymbolAddress((void**)&statsBase, g_stats);
    int* degiPtr = nullptr;
    cudaGetSymbolAddress((void**)&degiPtr, g_degi);
    int* cntPtr = nullptr;
    cudaGetSymbolAddress((void**)&cntPtr, g_cnt);

    static bool attr_done = false;
    if (!attr_done) {
        cudaFuncSetAttribute(k_att, cudaFuncAttributeMaxDynamicSharedMemorySize,
                             SM_FLOATS * (int)sizeof(float));
        cudaFuncSetAttribute(k_gemm0_scatter,
                             cudaFuncAttributeMaxDynamicSharedMemorySize, MM_SMEM);
        cudaFuncSetAttribute(k_gemm<HID, true>,
                             cudaFuncAttributeMaxDynamicSharedMemorySize, MM_SMEM);
        attr_done = true;
    }

    const int AGG_BLOCKS = NN / 8;                  // 6250 (exact)

    float* acc0 = accBase;
    float* acc1 = accBase + (size_t)NN * HID;
    float* acc2 = accBase + (size_t)2 * NN * HID;
    float* st0 = statsBase;
    float* st1 = statsBase + 2 * HID;
    float* st2 = statsBase + 4 * HID;

    // init via memset nodes (not kernel launches)
    cudaMemsetAsync(degiPtr, 0, NN * sizeof(int));
    cudaMemsetAsync(cntPtr, 0, NN * sizeof(int));
    cudaMemsetAsync(statsBase, 0, 3 * 2 * HID * sizeof(float));

    k_deg_count<<<(NE + 255) / 256, 256>>>(dst);
    k_scan1    <<<NSCANBLK, SCAN_BLK>>>();
    k_scan2    <<<1, 64>>>();
    k_gemm0_scatter<<<GEMM_BLOCKS + SCAT_BLOCKS, 256, MM_SMEM>>>(x, w0, src, dst);
    k_agg      <<<AGG_BLOCKS, 256>>>(b0, acc0, st0);

    k_gemm<HID, true><<<GEMM_BLOCKS, 256, MM_SMEM>>>(acc0, w1, st0, gamma, beta);
    k_agg      <<<AGG_BLOCKS, 256>>>(b1, acc1, st1);

    k_gemm<HID, true><<<GEMM_BLOCKS, 256, MM_SMEM>>>(acc1, w2, st1, gamma, beta);
    k_agg      <<<AGG_BLOCKS, 256>>>(b2, acc2, st2);

    k_att<<<512, 256, SM_FLOATS * (int)sizeof(float)>>>(dp, tp, dn, tn, WD, WT,
                                                        qD, qT, ow, ob,
                                                        gamma, beta, out);
}

// round 15
// speedup vs baseline: 1.0112x; 1.0112x over previous
#include <cuda_runtime.h>
#include <cuda_fp16.h>
#include <math.h>
#include <stdint.h>

#define NN   50000
#define NE   800000
#define IND  256
#define HID  128
#define OUTD 64
#define NB   4096
#define BN_EPS 1e-5f
#define SLOPE  0.01f

#define SCAN_BLK  1024
#define NSCANBLK  ((NN + SCAN_BLK - 1) / SCAN_BLK)   // 49

// ---------------- scratch (device globals; no allocation allowed) ----------
__device__ int    g_degi[NN];                      // int degree (no self loop)
__device__ int    g_off [NN];                      // local (per-scan-block) offsets
__device__ int    g_base[NSCANBLK];                // scan-block bases
__device__ int    g_bsum[NSCANBLK];                // scan-block sums
__device__ int    g_cnt [NN];                      // scatter counters
__device__ int    g_ssrc[NE];                      // src ids sorted by dst
__device__ __half g_s  [(size_t)NN * HID];         // dinv-scaled linear output (fp16)
__device__ float  g_accL[3][(size_t)NN * HID];     // per-layer pre-BN activations
__device__ float  g_stats[3][2 * HID];             // per-layer column sum / sumsq

// ---------------- bf16 helpers ------------------------------------------------
__device__ __forceinline__ uint32_t bf16pair(float f0, float f1) {
    uint32_t r;
    asm("cvt.rn.bf16x2.f32 %0, %1, %2;" : "=r"(r) : "f"(f1), "f"(f0));
    return r;
}
__device__ __forceinline__ float bf_lo(uint32_t p) { return __uint_as_float(p << 16); }
__device__ __forceinline__ float bf_hi(uint32_t p) { return __uint_as_float(p & 0xffff0000u); }

// m16n8k16 row.col bf16 MMA, fp32 accumulate
__device__ __forceinline__ void mma16816(float* c, const uint32_t* a, const uint32_t* b) {
    asm volatile(
        "mma.sync.aligned.m16n8k16.row.col.f32.bf16.bf16.f32 "
        "{%0,%1,%2,%3}, {%4,%5,%6,%7}, {%8,%9}, {%0,%1,%2,%3};"
        : "+f"(c[0]), "+f"(c[1]), "+f"(c[2]), "+f"(c[3])
        : "r"(a[0]), "r"(a[1]), "r"(a[2]), "r"(a[3]), "r"(b[0]), "r"(b[1]));
}

// ---------------- degree / CSR -------------------------------------------------
__global__ void k_deg_count(const int* __restrict__ dst) {
    int e = blockIdx.x * blockDim.x + threadIdx.x;
    if (e < NE) atomicAdd(&g_degi[dst[e]], 1);
}

// Parallel ordered scan, stage 1: per-block inclusive scan (1024 wide).
__global__ void k_scan1() {
    __shared__ int sc[SCAN_BLK];
    int t = threadIdx.x;
    int i = blockIdx.x * SCAN_BLK + t;
    int d = (i < NN) ? g_degi[i] : 0;
    sc[t] = d;
    __syncthreads();
    #pragma unroll
    for (int s = 1; s < SCAN_BLK; s <<= 1) {
        int v = (t >= s) ? sc[t - s] : 0;
        __syncthreads();
        sc[t] += v;
        __syncthreads();
    }
    if (i < NN) g_off[i] = sc[t] - d;
    if (t == SCAN_BLK - 1) g_bsum[blockIdx.x] = sc[t];
}

// Stage 2: exclusive scan of the 49 block sums (one tiny block).
__global__ void k_scan2() {
    __shared__ int sc[64];
    int t = threadIdx.x;           // 64 threads
    int v = (t < NSCANBLK) ? g_bsum[t] : 0;
    sc[t] = v;
    __syncthreads();
    #pragma unroll
    for (int s = 1; s < 64; s <<= 1) {
        int u = (t >= s) ? sc[t - s] : 0;
        __syncthreads();
        sc[t] += u;
        __syncthreads();
    }
    if (t < NSCANBLK) g_base[t] = sc[t] - v;   // exclusive
}

// ---------------- tensor GEMM (split-bf16, mma.sync) --------------------------
// D = Ahi*Bhi + Ahi*Blo + Alo*Bhi ; fp32 accum; epilogue stores fp16 to g_s.
// CTA 128x128, 8 warps (4m x 2n), warp tile 32x64. K chunked at 64.
#define TCH    64
#define TSTR   72
#define TILE_E (128 * TSTR)
#define MM_AHI 0
#define MM_ALO (TILE_E)
#define MM_BHI (2 * TILE_E)
#define MM_BLO (3 * TILE_E)
#define MM_SC  (4 * TILE_E * 2)
#define MM_SMEM (4 * TILE_E * 2 + 2 * HID * 4)

#define GEMM_BLOCKS ((NN + 127) / 128)          // 391
#define SCAT_BLOCKS ((NE + 255) / 256)          // 3125

template <int K, bool BN>
__device__ __forceinline__ void gemm_body(
    int blk,
    const float* __restrict__ X, const float* __restrict__ W,
    const float* __restrict__ stats, const float* __restrict__ gamma,
    const float* __restrict__ beta) {
    extern __shared__ char smc[];
    uint16_t* TB     = (uint16_t*)smc;
    float*    sScale = (float*)(smc + MM_SC);
    float*    sShift = sScale + HID;

    const int t    = threadIdx.x;
    const int wid  = t >> 5;
    const int lane = t & 31;
    const int gid  = lane >> 2;
    const int tig  = lane & 3;
    const int m0   = blk * 128;
    const int wm   = wid & 3;
    const int wn   = wid >> 2;

    if (BN && t < HID) {
        float mean = stats[t] * (1.0f / NN);
        float var  = stats[HID + t] * (1.0f / NN) - mean * mean;
        float sc   = gamma[t] * rsqrtf(var + BN_EPS);
        sScale[t] = sc;
        sShift[t] = beta[t] - mean * sc;
    }
    if (BN) __syncthreads();

    float acc[2][8][4];
    #pragma unroll
    for (int mi = 0; mi < 2; mi++)
        #pragma unroll
        for (int ni = 0; ni < 8; ni++)
            #pragma unroll
            for (int j = 0; j < 4; j++) acc[mi][ni][j] = 0.0f;

    const int NCH = K / TCH;
    for (int kc = 0; kc < NCH; kc++) {
        #pragma unroll
        for (int j = 0; j < 8; j++) {
            int idx = j * 256 + t;
            int row = idx >> 4;
            int c4  = (idx & 15) * 4;
            int m   = m0 + row;
            float4 v = (m < NN)
                ? *(const float4*)(X + (size_t)m * K + kc * TCH + c4)
                : make_float4(0.f, 0.f, 0.f, 0.f);
            if (BN) {
                int kg = kc * TCH + c4;
                v.x = v.x * sScale[kg + 0] + sShift[kg + 0];
                v.y = v.y * sScale[kg + 1] + sShift[kg + 1];
                v.z = v.z * sScale[kg + 2] + sShift[kg + 2];
                v.w = v.w * sScale[kg + 3] + sShift[kg + 3];
            }
            uint32_t hp0 = bf16pair(v.x, v.y);
            uint32_t hp1 = bf16pair(v.z, v.w);
            uint32_t lp0 = bf16pair(v.x - bf_lo(hp0), v.y - bf_hi(hp0));
            uint32_t lp1 = bf16pair(v.z - bf_lo(hp1), v.w - bf_hi(hp1));
            int eo = row * TSTR + c4;
            *(uint2*)(TB + MM_AHI + eo) = make_uint2(hp0, hp1);
            *(uint2*)(TB + MM_ALO + eo) = make_uint2(lp0, lp1);

            float4 w = *(const float4*)(W + (size_t)row * K + kc * TCH + c4);
            uint32_t whp0 = bf16pair(w.x, w.y);
            uint32_t whp1 = bf16pair(w.z, w.w);
            uint32_t wlp0 = bf16pair(w.x - bf_lo(whp0), w.y - bf_hi(whp0));
            uint32_t wlp1 = bf16pair(w.z - bf_lo(whp1), w.w - bf_hi(whp1));
            *(uint2*)(TB + MM_BHI + eo) = make_uint2(whp0, whp1);
            *(uint2*)(TB + MM_BLO + eo) = make_uint2(wlp0, wlp1);
        }
        __syncthreads();

        #pragma unroll
        for (int ks = 0; ks < 4; ks++) {
            const int kb = ks * 16 + 2 * tig;
            uint32_t ahi[2][4], alo[2][4];
            #pragma unroll
            for (int mi = 0; mi < 2; mi++) {
                int r = wm * 32 + mi * 16 + gid;
                ahi[mi][0] = *(const uint32_t*)(TB + MM_AHI + r * TSTR + kb);
                ahi[mi][1] = *(const uint32_t*)(TB + MM_AHI + (r + 8) * TSTR + kb);
                ahi[mi][2] = *(const uint32_t*)(TB + MM_AHI + r * TSTR + kb + 8);
                ahi[mi][3] = *(const uint32_t*)(TB + MM_AHI + (r + 8) * TSTR + kb + 8);
                alo[mi][0] = *(const uint32_t*)(TB + MM_ALO + r * TSTR + kb);
                alo[mi][1] = *(const uint32_t*)(TB + MM_ALO + (r + 8) * TSTR + kb);
                alo[mi][2] = *(const uint32_t*)(TB + MM_ALO + r * TSTR + kb + 8);
                alo[mi][3] = *(const uint32_t*)(TB + MM_ALO + (r + 8) * TSTR + kb + 8);
            }
            #pragma unroll
            for (int ni = 0; ni < 8; ni++) {
                int n = wn * 64 + ni * 8 + gid;
                uint32_t bh[2], bl[2];
                bh[0] = *(const uint32_t*)(TB + MM_BHI + n * TSTR + kb);
                bh[1] = *(const uint32_t*)(TB + MM_BHI + n * TSTR + kb + 8);
                bl[0] = *(const uint32_t*)(TB + MM_BLO + n * TSTR + kb);
                bl[1] = *(const uint32_t*)(TB + MM_BLO + n * TSTR + kb + 8);
                mma16816(acc[0][ni], ahi[0], bh);
                mma16816(acc[1][ni], ahi[1], bh);
                mma16816(acc[0][ni], alo[0], bh);
                mma16816(acc[1][ni], alo[1], bh);
                mma16816(acc[0][ni], ahi[0], bl);
                mma16816(acc[1][ni], ahi[1], bl);
            }
        }
        __syncthreads();
    }

    // epilogue: scale rows by dinv, store fp16 pairs
    __half2* S2 = (__half2*)g_s;               // row stride = 64 half2
    #pragma unroll
    for (int mi = 0; mi < 2; mi++) {
        int r0 = m0 + wm * 32 + mi * 16 + gid;
        int r1 = r0 + 8;
        float d0 = (r0 < NN) ? rsqrtf(1.0f + (float)g_degi[r0]) : 0.0f;
        float d1 = (r1 < NN) ? rsqrtf(1.0f + (float)g_degi[r1]) : 0.0f;
        #pragma unroll
        for (int ni = 0; ni < 8; ni++) {
            int col = wn * 64 + ni * 8 + 2 * tig;     // even
            if (r0 < NN)
                S2[(size_t)r0 * 64 + (col >> 1)] =
                    __floats2half2_rn(acc[mi][ni][0] * d0, acc[mi][ni][1] * d0);
            if (r1 < NN)
                S2[(size_t)r1 * 64 + (col >> 1)] =
                    __floats2half2_rn(acc[mi][ni][2] * d1, acc[mi][ni][3] * d1);
        }
    }
}

// plain GEMM kernel (layers 1, 2)
template <int K, bool BN>
__global__ void __launch_bounds__(256, 2)
k_gemm(const float* __restrict__ X, const float* __restrict__ W,
       const float* __restrict__ stats, const float* __restrict__ gamma,
       const float* __restrict__ beta) {
    gemm_body<K, BN>(blockIdx.x, X, W, stats, gamma, beta);
}

// fused layer-0 GEMM + CSR scatter (independent work, one launch).
__global__ void __launch_bounds__(256, 2)
k_gemm0_scatter(const float* __restrict__ X, const float* __restrict__ W,
                const int* __restrict__ src, const int* __restrict__ dst) {
    if (blockIdx.x >= GEMM_BLOCKS) {
        int e = (blockIdx.x - GEMM_BLOCKS) * 256 + threadIdx.x;
        if (e < NE) {
            int d = dst[e];
            int p = g_base[d >> 10] + g_off[d] + atomicAdd(&g_cnt[d], 1);
            g_ssrc[p] = src[e];
        }
        return;
    }
    gemm_body<IND, false>(blockIdx.x, X, W, nullptr, nullptr, nullptr);
}

// ---------------- fused CSR aggregation + bias/ReLU + stats ------------------
// fp16 gathers (256B/node row), fp32 accumulation.
__global__ void __launch_bounds__(256)
k_agg(const float* __restrict__ bias, float* __restrict__ outv,
      float* __restrict__ stats) {
    __shared__ float sSum[HID], sSq[HID];
    int t = threadIdx.x;
    if (t < HID) { sSum[t] = 0.0f; sSq[t] = 0.0f; }
    __syncthreads();

    int gw   = (blockIdx.x * 256 + t) >> 5;        // node id
    int lane = t & 31;
    int beg = g_base[gw >> 10] + g_off[gw];
    int end = beg + g_degi[gw];
    const uint2* S = (const uint2*)g_s;            // row stride = 32 uint2

    float4 acc;
    {
        uint2 p = S[(size_t)gw * 32 + lane];
        float2 a = __half22float2(*(__half2*)&p.x);
        float2 b = __half22float2(*(__half2*)&p.y);
        acc = make_float4(a.x, a.y, b.x, b.y);
    }
    int e = beg;
    for (; e + 4 <= end; e += 4) {
        int u0 = g_ssrc[e], u1 = g_ssrc[e + 1], u2 = g_ssrc[e + 2], u3 = g_ssrc[e + 3];
        uint2 p0 = S[(size_t)u0 * 32 + lane];
        uint2 p1 = S[(size_t)u1 * 32 + lane];
        uint2 p2 = S[(size_t)u2 * 32 + lane];
        uint2 p3 = S[(size_t)u3 * 32 + lane];
        float2 a0 = __half22float2(*(__half2*)&p0.x), b0 = __half22float2(*(__half2*)&p0.y);
        float2 a1 = __half22float2(*(__half2*)&p1.x), b1 = __half22float2(*(__half2*)&p1.y);
        float2 a2 = __half22float2(*(__half2*)&p2.x), b2 = __half22float2(*(__half2*)&p2.y);
        float2 a3 = __half22float2(*(__half2*)&p3.x), b3 = __half22float2(*(__half2*)&p3.y);
        acc.x += (a0.x + a1.x) + (a2.x + a3.x);
        acc.y += (a0.y + a1.y) + (a2.y + a3.y);
        acc.z += (b0.x + b1.x) + (b2.x + b3.x);
        acc.w += (b0.y + b1.y) + (b2.y + b3.y);
    }
    for (; e < end; e++) {
        int u = g_ssrc[e];
        uint2 p = S[(size_t)u * 32 + lane];
        float2 a = __half22float2(*(__half2*)&p.x);
        float2 b = __half22float2(*(__half2*)&p.y);
        acc.x += a.x; acc.y += a.y; acc.z += b.x; acc.w += b.y;
    }

    float dinv = rsqrtf(1.0f + (float)g_degi[gw]);
    float4 b4 = ((const float4*)bias)[lane];
    float4 v;
    v.x = fmaxf(acc.x * dinv + b4.x, 0.0f);
    v.y = fmaxf(acc.y * dinv + b4.y, 0.0f);
    v.z = fmaxf(acc.z * dinv + b4.z, 0.0f);
    v.w = fmaxf(acc.w * dinv + b4.w, 0.0f);
    ((float4*)outv)[(size_t)gw * 32 + lane] = v;

    int c = lane * 4;
    atomicAdd(&sSum[c + 0], v.x);     atomicAdd(&sSq[c + 0], v.x * v.x);
    atomicAdd(&sSum[c + 1], v.y);     atomicAdd(&sSq[c + 1], v.y * v.y);
    atomicAdd(&sSum[c + 2], v.z);     atomicAdd(&sSq[c + 2], v.z * v.z);
    atomicAdd(&sSum[c + 3], v.w);     atomicAdd(&sSq[c + 3], v.w * v.w);
    __syncthreads();

    if (t < 32) {
        float4 s = *(const float4*)&sSum[t * 4];
        atomicAdd((float4*)&stats[t * 4], s);
    } else if (t < 64) {
        int j = t - 32;
        float4 s = *(const float4*)&sSq[j * 4];
        atomicAdd((float4*)&stats[HID + j * 4], s);
    }
}

// ---------------- attention pooling + projection, 32 rows per block ---------
#define SM_W   0
#define SM_E   (SM_W + 128*132)
#define SM_P   (SM_E + 3*128*36)
#define SM_OW  (SM_P + 128*36)
#define SM_ES  (SM_OW + 128*66)
#define SM_AL  (SM_ES + 96)
#define SM_SC  (SM_AL + 96)
#define SM_SH  (SM_SC + 3*128)
#define SM_FLOATS (SM_SH + 3*128)

__global__ void k_att(const int* __restrict__ dp, const int* __restrict__ tp,
                      const int* __restrict__ dn, const int* __restrict__ tn,
                      const float* __restrict__ WD, const float* __restrict__ WT,
                      const float* __restrict__ qD, const float* __restrict__ qT,
                      const float* __restrict__ ow, const float* __restrict__ ob,
                      const float* __restrict__ gamma, const float* __restrict__ beta,
                      float* __restrict__ out) {
    extern __shared__ float sm[];
    __shared__ int s_node[32];

    const int tid = threadIdx.x;           // 256
    const int blk = blockIdx.x;            // 512
    const int grp = blk >> 7;
    const int jb  = (blk & 127) * 32;

    const int*   ids = (grp == 0) ? dp : (grp == 1) ? tp : (grp == 2) ? dn : tn;
    const float* W   = (grp & 1) ? WT : WD;
    const float* q   = (grp & 1) ? qT : qD;

    if (tid < 32) s_node[tid] = ids[jb + tid];
    if (tid < 96) sm[SM_ES + tid] = 0.0f;
    if (tid < 128) {
        #pragma unroll
        for (int l = 0; l < 3; l++) {
            const float* st = g_stats[l];
            float mean = st[tid] * (1.0f / NN);
            float var  = st[HID + tid] * (1.0f / NN) - mean * mean;
            float sc   = gamma[tid] * rsqrtf(var + BN_EPS);
            sm[SM_SC + l * 128 + tid] = sc;
            sm[SM_SH + l * 128 + tid] = beta[tid] - mean * sc;
        }
    }
    __syncthreads();

    #pragma unroll
    for (int i = 0; i < 64; i++) {
        int idx = i * 256 + tid;
        int t = idx >> 7, k = idx & 127;
        sm[SM_W + k * 132 + t] = W[idx];
    }
    #pragma unroll
    for (int i = 0; i < 32; i++) {
        int idx = i * 256 + tid;
        int o = idx >> 7, k = idx & 127;
        sm[SM_OW + k * 66 + o] = ow[idx];
    }
    #pragma unroll
    for (int l = 0; l < 3; l++)
        #pragma unroll
        for (int i = 0; i < 16; i++) {
            int idx = i * 256 + tid;
            int r = idx >> 7, k = idx & 127;
            float raw = g_accL[l][(size_t)s_node[r] * HID + k];
            sm[SM_E + ((l * 128 + k) * 36) + r] =
                raw * sm[SM_SC + l * 128 + k] + sm[SM_SH + l * 128 + k];
        }
    __syncthreads();

    const int tr = tid & 7;
    const int tt = tid >> 3;
    const int r0 = tr * 4;
    const int t0 = tt * 4;

    float ql0 = q[t0], ql1 = q[t0 + 1], ql2 = q[t0 + 2], ql3 = q[t0 + 3];

    for (int l = 0; l < 3; l++) {
        float acc[4][4];
        #pragma unroll
        for (int i = 0; i < 4; i++)
            #pragma unroll
            for (int j = 0; j < 4; j++) acc[i][j] = 0.0f;

        const float* eb = sm + SM_E + (l * 128) * 36;
        #pragma unroll 4
        for (int k = 0; k < 128; k++) {
            float4 a = *(const float4*)(eb + k * 36 + r0);
            float4 b = *(const float4*)(sm + SM_W + k * 132 + t0);
            acc[0][0] += a.x * b.x; acc[0][1] += a.x * b.y; acc[0][2] += a.x * b.z; acc[0][3] += a.x * b.w;
            acc[1][0] += a.y * b.x; acc[1][1] += a.y * b.y; acc[1][2] += a.y * b.z; acc[1][3] += a.y * b.w;
            acc[2][0] += a.z * b.x; acc[2][1] += a.z * b.y; acc[2][2] += a.z * b.z; acc[2][3] += a.z * b.w;
            acc[3][0] += a.w * b.x; acc[3][1] += a.w * b.y; acc[3][2] += a.w * b.z; acc[3][3] += a.w * b.w;
        }
        #pragma unroll
        for (int i = 0; i < 4; i++) {
            float h0 = acc[i][0], h1 = acc[i][1], h2 = acc[i][2], h3 = acc[i][3];
            h0 = (h0 > 0.0f) ? h0 : SLOPE * h0;
            h1 = (h1 > 0.0f) ? h1 : SLOPE * h1;
            h2 = (h2 > 0.0f) ? h2 : SLOPE * h2;
            h3 = (h3 > 0.0f) ? h3 : SLOPE * h3;
            float pe = h0 * ql0 + h1 * ql1 + h2 * ql2 + h3 * ql3;
            atomicAdd(&sm[SM_ES + l * 32 + r0 + i], pe);
        }
    }
    __syncthreads();

    if (tid < 32) {
        float e0 = sm[SM_ES + tid], e1 = sm[SM_ES + 32 + tid], e2 = sm[SM_ES + 64 + tid];
        float m  = fmaxf(e0, fmaxf(e1, e2));
        float a0 = expf(e0 - m), a1 = expf(e1 - m), a2 = expf(e2 - m);
        float s  = 1.0f / (a0 + a1 + a2);
        sm[SM_AL + tid]      = a0 * s;
        sm[SM_AL + 32 + tid] = a1 * s;
        sm[SM_AL + 64 + tid] = a2 * s;
    }
    __syncthreads();

    #pragma unroll
    for (int i = 0; i < 16; i++) {
        int idx = i * 256 + tid;
        int k = idx >> 5, r = idx & 31;
        float v = sm[SM_AL + r]      * sm[SM_E + (0 * 128 + k) * 36 + r]
                + sm[SM_AL + 32 + r] * sm[SM_E + (1 * 128 + k) * 36 + r]
                + sm[SM_AL + 64 + r] * sm[SM_E + (2 * 128 + k) * 36 + r];
        sm[SM_P + k * 36 + r] = v;
    }
    __syncthreads();

    {
        const int o0 = tt * 2;
        float a0 = 0, a1 = 0, b0 = 0, b1 = 0, c0 = 0, c1 = 0, d0 = 0, d1 = 0;
        #pragma unroll 4
        for (int k = 0; k < 128; k++) {
            float4 p = *(const float4*)(sm + SM_P + k * 36 + r0);
            float2 w2 = *(const float2*)(sm + SM_OW + k * 66 + o0);
            a0 += p.x * w2.x; a1 += p.x * w2.y;
            b0 += p.y * w2.x; b1 += p.y * w2.y;
            c0 += p.z * w2.x; c1 += p.z * w2.y;
            d0 += p.w * w2.x; d1 += p.w * w2.y;
        }
        float ob0 = ob[o0], ob1 = ob[o0 + 1];
        int row = blk * 32 + r0;
        out[(size_t)(row + 0) * OUTD + o0]     = a0 + ob0;
        out[(size_t)(row + 0) * OUTD + o0 + 1] = a1 + ob1;
        out[(size_t)(row + 1) * OUTD + o0]     = b0 + ob0;
        out[(size_t)(row + 1) * OUTD + o0 + 1] = b1 + ob1;
        out[(size_t)(row + 2) * OUTD + o0]     = c0 + ob0;
        out[(size_t)(row + 2) * OUTD + o0 + 1] = c1 + ob1;
        out[(size_t)(row + 3) * OUTD + o0]     = d0 + ob0;
        out[(size_t)(row + 3) * OUTD + o0 + 1] = d1 + ob1;
    }
}

// ---------------- launch -----------------------------------------------------
extern "C" void kernel_launch(void* const* d_in, const int* in_sizes, int n_in,
                              void* d_out, int out_size) {
    const float* x     = (const float*)d_in[0];
    const int*   ei    = (const int*)  d_in[1];
    const int*   dp    = (const int*)  d_in[2];
    const int*   tp    = (const int*)  d_in[3];
    const int*   dn    = (const int*)  d_in[4];
    const int*   tn    = (const int*)  d_in[5];
    const float* w0    = (const float*)d_in[7];
    const float* b0    = (const float*)d_in[8];
    const float* w1    = (const float*)d_in[9];
    const float* b1    = (const float*)d_in[10];
    const float* w2    = (const float*)d_in[11];
    const float* b2    = (const float*)d_in[12];
    const float* gamma = (const float*)d_in[13];
    const float* beta  = (const float*)d_in[14];
    const float* WD    = (const float*)d_in[15];
    const float* WT    = (const float*)d_in[16];
    const float* qD    = (const float*)d_in[17];
    const float* qT    = (const float*)d_in[18];
    const float* ow    = (const float*)d_in[19];
    const float* ob    = (const float*)d_in[20];
    float*       out   = (float*)d_out;

    const int* src = ei;
    const int* dst = ei + NE;

    float* accBase = nullptr;
    cudaGetSymbolAddress((void**)&accBase, g_accL);
    float* statsBase = nullptr;
    cudaGetSymbolAddress((void**)&statsBase, g_stats);
    int* degiPtr = nullptr;
    cudaGetSymbolAddress((void**)&degiPtr, g_degi);
    int* cntPtr = nullptr;
    cudaGetSymbolAddress((void**)&cntPtr, g_cnt);

    static bool attr_done = false;
    if (!attr_done) {
        cudaFuncSetAttribute(k_att, cudaFuncAttributeMaxDynamicSharedMemorySize,
                             SM_FLOATS * (int)sizeof(float));
        cudaFuncSetAttribute(k_gemm0_scatter,
                             cudaFuncAttributeMaxDynamicSharedMemorySize, MM_SMEM);
        cudaFuncSetAttribute(k_gemm<HID, true>,
                             cudaFuncAttributeMaxDynamicSharedMemorySize, MM_SMEM);
        attr_done = true;
    }

    const int AGG_BLOCKS = NN / 8;                  // 6250 (exact)

    float* acc0 = accBase;
    float* acc1 = accBase + (size_t)NN * HID;
    float* acc2 = accBase + (size_t)2 * NN * HID;
    float* st0 = statsBase;
    float* st1 = statsBase + 2 * HID;
    float* st2 = statsBase + 4 * HID;

    // init via memset nodes (not kernel launches)
    cudaMemsetAsync(degiPtr, 0, NN * sizeof(int));
    cudaMemsetAsync(cntPtr, 0, NN * sizeof(int));
    cudaMemsetAsync(statsBase, 0, 3 * 2 * HID * sizeof(float));

    k_deg_count<<<(NE + 255) / 256, 256>>>(dst);
    k_scan1    <<<NSCANBLK, SCAN_BLK>>>();
    k_scan2    <<<1, 64>>>();
    k_gemm0_scatter<<<GEMM_BLOCKS + SCAT_BLOCKS, 256, MM_SMEM>>>(x, w0, src, dst);
    k_agg      <<<AGG_BLOCKS, 256>>>(b0, acc0, st0);

    k_gemm<HID, true><<<GEMM_BLOCKS, 256, MM_SMEM>>>(acc0, w1, st0, gamma, beta);
    k_agg      <<<AGG_BLOCKS, 256>>>(b1, acc1, st1);

    k_gemm<HID, true><<<GEMM_BLOCKS, 256, MM_SMEM>>>(acc1, w2, st1, gamma, beta);
    k_agg      <<<AGG_BLOCKS, 256>>>(b2, acc2, st2);

    k_att<<<512, 256, SM_FLOATS * (int)sizeof(float)>>>(dp, tp, dn, tn, WD, WT,
                                                        qD, qT, ow, ob,
                                                        gamma, beta, out);
}

// round 16
// speedup vs baseline: 1.0739x; 1.0620x over previous
#include <cuda_runtime.h>
#include <cuda_fp16.h>
#include <math.h>
#include <stdint.h>

#define NN   50000
#define NE   800000
#define IND  256
#define HID  128
#define OUTD 64
#define NB   4096
#define BN_EPS 1e-5f
#define SLOPE  0.01f

// ---------------- scratch (device globals; no allocation allowed) ----------
__device__ int    g_degi[NN];                      // int degree (no self loop)
__device__ int    g_off [NN];                      // CSR offsets (ordered scan)
__device__ int    g_cnt [NN];                      // scatter counters
__device__ int    g_ssrc[NE];                      // src ids sorted by dst
__device__ __half g_s  [(size_t)NN * HID];         // dinv-scaled linear output (fp16)
__device__ float  g_accL[3][(size_t)NN * HID];     // per-layer pre-BN activations
__device__ float  g_stats[3][2 * HID];             // per-layer column sum / sumsq

// ---------------- bf16 helpers ------------------------------------------------
__device__ __forceinline__ uint32_t bf16pair(float f0, float f1) {
    uint32_t r;
    asm("cvt.rn.bf16x2.f32 %0, %1, %2;" : "=r"(r) : "f"(f1), "f"(f0));
    return r;
}
__device__ __forceinline__ float bf_lo(uint32_t p) { return __uint_as_float(p << 16); }
__device__ __forceinline__ float bf_hi(uint32_t p) { return __uint_as_float(p & 0xffff0000u); }

// m16n8k16 row.col bf16 MMA, fp32 accumulate
__device__ __forceinline__ void mma16816(float* c, const uint32_t* a, const uint32_t* b) {
    asm volatile(
        "mma.sync.aligned.m16n8k16.row.col.f32.bf16.bf16.f32 "
        "{%0,%1,%2,%3}, {%4,%5,%6,%7}, {%8,%9}, {%0,%1,%2,%3};"
        : "+f"(c[0]), "+f"(c[1]), "+f"(c[2]), "+f"(c[3])
        : "r"(a[0]), "r"(a[1]), "r"(a[2]), "r"(a[3]), "r"(b[0]), "r"(b[1]));
}

// ---------------- degree / CSR -------------------------------------------------
__global__ void k_deg_count(const int* __restrict__ dst) {
    int e = blockIdx.x * blockDim.x + threadIdx.x;
    if (e < NE) atomicAdd(&g_degi[dst[e]], 1);
}
__global__ void k_scan() {                      // 1 block, 1024 threads (ordered)
    const int PER = (NN + 1023) / 1024;         // 49
    int t = threadIdx.x;
    int base = t * PER;
    int sum = 0;
    for (int j = 0; j < PER; j++) { int i = base + j; if (i < NN) sum += g_degi[i]; }
    __shared__ int tmp[1024];
    tmp[t] = sum;
    __syncthreads();
    for (int d = 1; d < 1024; d <<= 1) {
        int v = (t >= d) ? tmp[t - d] : 0;
        __syncthreads();
        tmp[t] += v;
        __syncthreads();
    }
    int off = (t == 0) ? 0 : tmp[t - 1];
    for (int j = 0; j < PER; j++) {
        int i = base + j;
        if (i < NN) { g_off[i] = off; off += g_degi[i]; }
    }
}

// ---------------- tensor GEMM (split-bf16, mma.sync) --------------------------
// D = Ahi*Bhi + Ahi*Blo + Alo*Bhi ; fp32 accum; epilogue stores fp16 to g_s.
// CTA 128x128, 8 warps (4m x 2n), warp tile 32x64. K chunked at 64.
#define TCH    64
#define TSTR   72
#define TILE_E (128 * TSTR)
#define MM_AHI 0
#define MM_ALO (TILE_E)
#define MM_BHI (2 * TILE_E)
#define MM_BLO (3 * TILE_E)
#define MM_SC  (4 * TILE_E * 2)
#define MM_SMEM (4 * TILE_E * 2 + 2 * HID * 4)

#define GEMM_BLOCKS ((NN + 127) / 128)          // 391
#define SCAT_BLOCKS ((NE + 255) / 256)          // 3125

template <int K, bool BN>
__device__ __forceinline__ void gemm_body(
    int blk,
    const float* __restrict__ X, const float* __restrict__ W,
    const float* __restrict__ stats, const float* __restrict__ gamma,
    const float* __restrict__ beta) {
    extern __shared__ char smc[];
    uint16_t* TB     = (uint16_t*)smc;
    float*    sScale = (float*)(smc + MM_SC);
    float*    sShift = sScale + HID;

    const int t    = threadIdx.x;
    const int wid  = t >> 5;
    const int lane = t & 31;
    const int gid  = lane >> 2;
    const int tig  = lane & 3;
    const int m0   = blk * 128;
    const int wm   = wid & 3;
    const int wn   = wid >> 2;

    if (BN && t < HID) {
        float mean = stats[t] * (1.0f / NN);
        float var  = stats[HID + t] * (1.0f / NN) - mean * mean;
        float sc   = gamma[t] * rsqrtf(var + BN_EPS);
        sScale[t] = sc;
        sShift[t] = beta[t] - mean * sc;
    }
    if (BN) __syncthreads();

    float acc[2][8][4];
    #pragma unroll
    for (int mi = 0; mi < 2; mi++)
        #pragma unroll
        for (int ni = 0; ni < 8; ni++)
            #pragma unroll
            for (int j = 0; j < 4; j++) acc[mi][ni][j] = 0.0f;

    const int NCH = K / TCH;
    for (int kc = 0; kc < NCH; kc++) {
        #pragma unroll
        for (int j = 0; j < 8; j++) {
            int idx = j * 256 + t;
            int row = idx >> 4;
            int c4  = (idx & 15) * 4;
            int m   = m0 + row;
            float4 v = (m < NN)
                ? *(const float4*)(X + (size_t)m * K + kc * TCH + c4)
                : make_float4(0.f, 0.f, 0.f, 0.f);
            if (BN) {
                int kg = kc * TCH + c4;
                v.x = v.x * sScale[kg + 0] + sShift[kg + 0];
                v.y = v.y * sScale[kg + 1] + sShift[kg + 1];
                v.z = v.z * sScale[kg + 2] + sShift[kg + 2];
                v.w = v.w * sScale[kg + 3] + sShift[kg + 3];
            }
            uint32_t hp0 = bf16pair(v.x, v.y);
            uint32_t hp1 = bf16pair(v.z, v.w);
            uint32_t lp0 = bf16pair(v.x - bf_lo(hp0), v.y - bf_hi(hp0));
            uint32_t lp1 = bf16pair(v.z - bf_lo(hp1), v.w - bf_hi(hp1));
            int eo = row * TSTR + c4;
            *(uint2*)(TB + MM_AHI + eo) = make_uint2(hp0, hp1);
            *(uint2*)(TB + MM_ALO + eo) = make_uint2(lp0, lp1);

            float4 w = *(const float4*)(W + (size_t)row * K + kc * TCH + c4);
            uint32_t whp0 = bf16pair(w.x, w.y);
            uint32_t whp1 = bf16pair(w.z, w.w);
            uint32_t wlp0 = bf16pair(w.x - bf_lo(whp0), w.y - bf_hi(whp0));
            uint32_t wlp1 = bf16pair(w.z - bf_lo(whp1), w.w - bf_hi(whp1));
            *(uint2*)(TB + MM_BHI + eo) = make_uint2(whp0, whp1);
            *(uint2*)(TB + MM_BLO + eo) = make_uint2(wlp0, wlp1);
        }
        __syncthreads();

        #pragma unroll
        for (int ks = 0; ks < 4; ks++) {
            const int kb = ks * 16 + 2 * tig;
            uint32_t ahi[2][4], alo[2][4];
            #pragma unroll
            for (int mi = 0; mi < 2; mi++) {
                int r = wm * 32 + mi * 16 + gid;
                ahi[mi][0] = *(const uint32_t*)(TB + MM_AHI + r * TSTR + kb);
                ahi[mi][1] = *(const uint32_t*)(TB + MM_AHI + (r + 8) * TSTR + kb);
                ahi[mi][2] = *(const uint32_t*)(TB + MM_AHI + r * TSTR + kb + 8);
                ahi[mi][3] = *(const uint32_t*)(TB + MM_AHI + (r + 8) * TSTR + kb + 8);
                alo[mi][0] = *(const uint32_t*)(TB + MM_ALO + r * TSTR + kb);
                alo[mi][1] = *(const uint32_t*)(TB + MM_ALO + (r + 8) * TSTR + kb);
                alo[mi][2] = *(const uint32_t*)(TB + MM_ALO + r * TSTR + kb + 8);
                alo[mi][3] = *(const uint32_t*)(TB + MM_ALO + (r + 8) * TSTR + kb + 8);
            }
            #pragma unroll
            for (int ni = 0; ni < 8; ni++) {
                int n = wn * 64 + ni * 8 + gid;
                uint32_t bh[2], bl[2];
                bh[0] = *(const uint32_t*)(TB + MM_BHI + n * TSTR + kb);
                bh[1] = *(const uint32_t*)(TB + MM_BHI + n * TSTR + kb + 8);
                bl[0] = *(const uint32_t*)(TB + MM_BLO + n * TSTR + kb);
                bl[1] = *(const uint32_t*)(TB + MM_BLO + n * TSTR + kb + 8);
                mma16816(acc[0][ni], ahi[0], bh);
                mma16816(acc[1][ni], ahi[1], bh);
                mma16816(acc[0][ni], alo[0], bh);
                mma16816(acc[1][ni], alo[1], bh);
                mma16816(acc[0][ni], ahi[0], bl);
                mma16816(acc[1][ni], ahi[1], bl);
            }
        }
        __syncthreads();
    }

    // epilogue: scale rows by dinv, store fp16 pairs
    __half2* S2 = (__half2*)g_s;               // row stride = 64 half2
    #pragma unroll
    for (int mi = 0; mi < 2; mi++) {
        int r0 = m0 + wm * 32 + mi * 16 + gid;
        int r1 = r0 + 8;
        float d0 = (r0 < NN) ? rsqrtf(1.0f + (float)g_degi[r0]) : 0.0f;
        float d1 = (r1 < NN) ? rsqrtf(1.0f + (float)g_degi[r1]) : 0.0f;
        #pragma unroll
        for (int ni = 0; ni < 8; ni++) {
            int col = wn * 64 + ni * 8 + 2 * tig;     // even
            if (r0 < NN)
                S2[(size_t)r0 * 64 + (col >> 1)] =
                    __floats2half2_rn(acc[mi][ni][0] * d0, acc[mi][ni][1] * d0);
            if (r1 < NN)
                S2[(size_t)r1 * 64 + (col >> 1)] =
                    __floats2half2_rn(acc[mi][ni][2] * d1, acc[mi][ni][3] * d1);
        }
    }
}

// plain GEMM kernel (layers 1, 2)
template <int K, bool BN>
__global__ void __launch_bounds__(256, 2)
k_gemm(const float* __restrict__ X, const float* __restrict__ W,
       const float* __restrict__ stats, const float* __restrict__ gamma,
       const float* __restrict__ beta) {
    gemm_body<K, BN>(blockIdx.x, X, W, stats, gamma, beta);
}

// fused layer-0 GEMM + CSR scatter (independent work, one launch).
__global__ void __launch_bounds__(256, 2)
k_gemm0_scatter(const float* __restrict__ X, const float* __restrict__ W,
                const int* __restrict__ src, const int* __restrict__ dst) {
    if (blockIdx.x >= GEMM_BLOCKS) {
        int e = (blockIdx.x - GEMM_BLOCKS) * 256 + threadIdx.x;
        if (e < NE) {
            int d = dst[e];
            int p = g_off[d] + atomicAdd(&g_cnt[d], 1);
            g_ssrc[p] = src[e];
        }
        return;
    }
    gemm_body<IND, false>(blockIdx.x, X, W, nullptr, nullptr, nullptr);
}

// ---------------- fused CSR aggregation + bias/ReLU + stats ------------------
// fp16 gathers (256B/node row), fp32 accumulation.
__global__ void __launch_bounds__(256)
k_agg(const float* __restrict__ bias, float* __restrict__ outv,
      float* __restrict__ stats) {
    __shared__ float sSum[HID], sSq[HID];
    int t = threadIdx.x;
    if (t < HID) { sSum[t] = 0.0f; sSq[t] = 0.0f; }
    __syncthreads();

    int gw   = (blockIdx.x * 256 + t) >> 5;        // node id
    int lane = t & 31;
    int beg = g_off[gw];
    int end = beg + g_degi[gw];
    const uint2* S = (const uint2*)g_s;            // row stride = 32 uint2 (4 halfs each)

    // self-loop
    float4 acc;
    {
        uint2 p = S[(size_t)gw * 32 + lane];
        float2 a = __half22float2(*(__half2*)&p.x);
        float2 b = __half22float2(*(__half2*)&p.y);
        acc = make_float4(a.x, a.y, b.x, b.y);
    }
    int e = beg;
    for (; e + 4 <= end; e += 4) {
        int u0 = g_ssrc[e], u1 = g_ssrc[e + 1], u2 = g_ssrc[e + 2], u3 = g_ssrc[e + 3];
        uint2 p0 = S[(size_t)u0 * 32 + lane];
        uint2 p1 = S[(size_t)u1 * 32 + lane];
        uint2 p2 = S[(size_t)u2 * 32 + lane];
        uint2 p3 = S[(size_t)u3 * 32 + lane];
        float2 a0 = __half22float2(*(__half2*)&p0.x), b0 = __half22float2(*(__half2*)&p0.y);
        float2 a1 = __half22float2(*(__half2*)&p1.x), b1 = __half22float2(*(__half2*)&p1.y);
        float2 a2 = __half22float2(*(__half2*)&p2.x), b2 = __half22float2(*(__half2*)&p2.y);
        float2 a3 = __half22float2(*(__half2*)&p3.x), b3 = __half22float2(*(__half2*)&p3.y);
        acc.x += (a0.x + a1.x) + (a2.x + a3.x);
        acc.y += (a0.y + a1.y) + (a2.y + a3.y);
        acc.z += (b0.x + b1.x) + (b2.x + b3.x);
        acc.w += (b0.y + b1.y) + (b2.y + b3.y);
    }
    for (; e < end; e++) {
        int u = g_ssrc[e];
        uint2 p = S[(size_t)u * 32 + lane];
        float2 a = __half22float2(*(__half2*)&p.x);
        float2 b = __half22float2(*(__half2*)&p.y);
        acc.x += a.x; acc.y += a.y; acc.z += b.x; acc.w += b.y;
    }

    float dinv = rsqrtf(1.0f + (float)g_degi[gw]);
    float4 b4 = ((const float4*)bias)[lane];
    float4 v;
    v.x = fmaxf(acc.x * dinv + b4.x, 0.0f);
    v.y = fmaxf(acc.y * dinv + b4.y, 0.0f);
    v.z = fmaxf(acc.z * dinv + b4.z, 0.0f);
    v.w = fmaxf(acc.w * dinv + b4.w, 0.0f);
    ((float4*)outv)[(size_t)gw * 32 + lane] = v;

    int c = lane * 4;
    atomicAdd(&sSum[c + 0], v.x);     atomicAdd(&sSq[c + 0], v.x * v.x);
    atomicAdd(&sSum[c + 1], v.y);     atomicAdd(&sSq[c + 1], v.y * v.y);
    atomicAdd(&sSum[c + 2], v.z);     atomicAdd(&sSq[c + 2], v.z * v.z);
    atomicAdd(&sSum[c + 3], v.w);     atomicAdd(&sSq[c + 3], v.w * v.w);
    __syncthreads();

    if (t < 32) {
        float4 s = *(const float4*)&sSum[t * 4];
        atomicAdd((float4*)&stats[t * 4], s);
    } else if (t < 64) {
        int j = t - 32;
        float4 s = *(const float4*)&sSq[j * 4];
        atomicAdd((float4*)&stats[HID + j * 4], s);
    }
}

// ---------------- attention pooling + projection, 32 rows per block ---------
#define SM_W   0
#define SM_E   (SM_W + 128*132)
#define SM_P   (SM_E + 3*128*36)
#define SM_OW  (SM_P + 128*36)
#define SM_ES  (SM_OW + 128*66)
#define SM_AL  (SM_ES + 96)
#define SM_SC  (SM_AL + 96)
#define SM_SH  (SM_SC + 3*128)
#define SM_FLOATS (SM_SH + 3*128)

__global__ void k_att(const int* __restrict__ dp, const int* __restrict__ tp,
                      const int* __restrict__ dn, const int* __restrict__ tn,
                      const float* __restrict__ WD, const float* __restrict__ WT,
                      const float* __restrict__ qD, const float* __restrict__ qT,
                      const float* __restrict__ ow, const float* __restrict__ ob,
                      const float* __restrict__ gamma, const float* __restrict__ beta,
                      float* __restrict__ out) {
    extern __shared__ float sm[];
    __shared__ int s_node[32];

    const int tid = threadIdx.x;           // 256
    const int blk = blockIdx.x;            // 512
    const int grp = blk >> 7;
    const int jb  = (blk & 127) * 32;

    const int*   ids = (grp == 0) ? dp : (grp == 1) ? tp : (grp == 2) ? dn : tn;
    const float* W   = (grp & 1) ? WT : WD;
    const float* q   = (grp & 1) ? qT : qD;

    if (tid < 32) s_node[tid] = ids[jb + tid];
    if (tid < 96) sm[SM_ES + tid] = 0.0f;
    if (tid < 128) {
        #pragma unroll
        for (int l = 0; l < 3; l++) {
            const float* st = g_stats[l];
            float mean = st[tid] * (1.0f / NN);
            float var  = st[HID + tid] * (1.0f / NN) - mean * mean;
            float sc   = gamma[tid] * rsqrtf(var + BN_EPS);
            sm[SM_SC + l * 128 + tid] = sc;
            sm[SM_SH + l * 128 + tid] = beta[tid] - mean * sc;
        }
    }
    __syncthreads();

    #pragma unroll
    for (int i = 0; i < 64; i++) {
        int idx = i * 256 + tid;
        int t = idx >> 7, k = idx & 127;
        sm[SM_W + k * 132 + t] = W[idx];
    }
    #pragma unroll
    for (int i = 0; i < 32; i++) {
        int idx = i * 256 + tid;
        int o = idx >> 7, k = idx & 127;
        sm[SM_OW + k * 66 + o] = ow[idx];
    }
    #pragma unroll
    for (int l = 0; l < 3; l++)
        #pragma unroll
        for (int i = 0; i < 16; i++) {
            int idx = i * 256 + tid;
            int r = idx >> 7, k = idx & 127;
            float raw = g_accL[l][(size_t)s_node[r] * HID + k];
            sm[SM_E + ((l * 128 + k) * 36) + r] =
                raw * sm[SM_SC + l * 128 + k] + sm[SM_SH + l * 128 + k];
        }
    __syncthreads();

    const int tr = tid & 7;
    const int tt = tid >> 3;
    const int r0 = tr * 4;
    const int t0 = tt * 4;

    float ql0 = q[t0], ql1 = q[t0 + 1], ql2 = q[t0 + 2], ql3 = q[t0 + 3];

    for (int l = 0; l < 3; l++) {
        float acc[4][4];
        #pragma unroll
        for (int i = 0; i < 4; i++)
            #pragma unroll
            for (int j = 0; j < 4; j++) acc[i][j] = 0.0f;

        const float* eb = sm + SM_E + (l * 128) * 36;
        #pragma unroll 4
        for (int k = 0; k < 128; k++) {
            float4 a = *(const float4*)(eb + k * 36 + r0);
            float4 b = *(const float4*)(sm + SM_W + k * 132 + t0);
            acc[0][0] += a.x * b.x; acc[0][1] += a.x * b.y; acc[0][2] += a.x * b.z; acc[0][3] += a.x * b.w;
            acc[1][0] += a.y * b.x; acc[1][1] += a.y * b.y; acc[1][2] += a.y * b.z; acc[1][3] += a.y * b.w;
            acc[2][0] += a.z * b.x; acc[2][1] += a.z * b.y; acc[2][2] += a.z * b.z; acc[2][3] += a.z * b.w;
            acc[3][0] += a.w * b.x; acc[3][1] += a.w * b.y; acc[3][2] += a.w * b.z; acc[3][3] += a.w * b.w;
        }
        #pragma unroll
        for (int i = 0; i < 4; i++) {
            float h0 = acc[i][0], h1 = acc[i][1], h2 = acc[i][2], h3 = acc[i][3];
            h0 = (h0 > 0.0f) ? h0 : SLOPE * h0;
            h1 = (h1 > 0.0f) ? h1 : SLOPE * h1;
            h2 = (h2 > 0.0f) ? h2 : SLOPE * h2;
            h3 = (h3 > 0.0f) ? h3 : SLOPE * h3;
            float pe = h0 * ql0 + h1 * ql1 + h2 * ql2 + h3 * ql3;
            atomicAdd(&sm[SM_ES + l * 32 + r0 + i], pe);
        }
    }
    __syncthreads();

    if (tid < 32) {
        float e0 = sm[SM_ES + tid], e1 = sm[SM_ES + 32 + tid], e2 = sm[SM_ES + 64 + tid];
        float m  = fmaxf(e0, fmaxf(e1, e2));
        float a0 = expf(e0 - m), a1 = expf(e1 - m), a2 = expf(e2 - m);
        float s  = 1.0f / (a0 + a1 + a2);
        sm[SM_AL + tid]      = a0 * s;
        sm[SM_AL + 32 + tid] = a1 * s;
        sm[SM_AL + 64 + tid] = a2 * s;
    }
    __syncthreads();

    #pragma unroll
    for (int i = 0; i < 16; i++) {
        int idx = i * 256 + tid;
        int k = idx >> 5, r = idx & 31;
        float v = sm[SM_AL + r]      * sm[SM_E + (0 * 128 + k) * 36 + r]
                + sm[SM_AL + 32 + r] * sm[SM_E + (1 * 128 + k) * 36 + r]
                + sm[SM_AL + 64 + r] * sm[SM_E + (2 * 128 + k) * 36 + r];
        sm[SM_P + k * 36 + r] = v;
    }
    __syncthreads();

    {
        const int o0 = tt * 2;
        float a0 = 0, a1 = 0, b0 = 0, b1 = 0, c0 = 0, c1 = 0, d0 = 0, d1 = 0;
        #pragma unroll 4
        for (int k = 0; k < 128; k++) {
            float4 p = *(const float4*)(sm + SM_P + k * 36 + r0);
            float2 w2 = *(const float2*)(sm + SM_OW + k * 66 + o0);
            a0 += p.x * w2.x; a1 += p.x * w2.y;
            b0 += p.y * w2.x; b1 += p.y * w2.y;
            c0 += p.z * w2.x; c1 += p.z * w2.y;
            d0 += p.w * w2.x; d1 += p.w * w2.y;
        }
        float ob0 = ob[o0], ob1 = ob[o0 + 1];
        int row = blk * 32 + r0;
        out[(size_t)(row + 0) * OUTD + o0]     = a0 + ob0;
        out[(size_t)(row + 0) * OUTD + o0 + 1] = a1 + ob1;
        out[(size_t)(row + 1) * OUTD + o0]     = b0 + ob0;
        out[(size_t)(row + 1) * OUTD + o0 + 1] = b1 + ob1;
        out[(size_t)(row + 2) * OUTD + o0]     = c0 + ob0;
        out[(size_t)(row + 2) * OUTD + o0 + 1] = c1 + ob1;
        out[(size_t)(row + 3) * OUTD + o0]     = d0 + ob0;
        out[(size_t)(row + 3) * OUTD + o0 + 1] = d1 + ob1;
    }
}

// ---------------- launch -----------------------------------------------------
extern "C" void kernel_launch(void* const* d_in, const int* in_sizes, int n_in,
                              void* d_out, int out_size) {
    const float* x     = (const float*)d_in[0];
    const int*   ei    = (const int*)  d_in[1];
    const int*   dp    = (const int*)  d_in[2];
    const int*   tp    = (const int*)  d_in[3];
    const int*   dn    = (const int*)  d_in[4];
    const int*   tn    = (const int*)  d_in[5];
    const float* w0    = (const float*)d_in[7];
    const float* b0    = (const float*)d_in[8];
    const float* w1    = (const float*)d_in[9];
    const float* b1    = (const float*)d_in[10];
    const float* w2    = (const float*)d_in[11];
    const float* b2    = (const float*)d_in[12];
    const float* gamma = (const float*)d_in[13];
    const float* beta  = (const float*)d_in[14];
    const float* WD    = (const float*)d_in[15];
    const float* WT    = (const float*)d_in[16];
    const float* qD    = (const float*)d_in[17];
    const float* qT    = (const float*)d_in[18];
    const float* ow    = (const float*)d_in[19];
    const float* ob    = (const float*)d_in[20];
    float*       out   = (float*)d_out;

    const int* src = ei;
    const int* dst = ei + NE;

    float* accBase = nullptr;
    cudaGetSymbolAddress((void**)&accBase, g_accL);
    float* statsBase = nullptr;
    cudaGetSymbolAddress((void**)&statsBase, g_stats);
    int* degiPtr = nullptr;
    cudaGetSymbolAddress((void**)&degiPtr, g_degi);
    int* cntPtr = nullptr;
    cudaGetSymbolAddress((void**)&cntPtr, g_cnt);

    static bool attr_done = false;
    if (!attr_done) {
        cudaFuncSetAttribute(k_att, cudaFuncAttributeMaxDynamicSharedMemorySize,
                             SM_FLOATS * (int)sizeof(float));
        cudaFuncSetAttribute(k_gemm0_scatter,
                             cudaFuncAttributeMaxDynamicSharedMemorySize, MM_SMEM);
        cudaFuncSetAttribute(k_gemm<HID, true>,
                             cudaFuncAttributeMaxDynamicSharedMemorySize, MM_SMEM);
        attr_done = true;
    }

    const int AGG_BLOCKS = NN / 8;                  // 6250 (exact)

    float* acc0 = accBase;
    float* acc1 = accBase + (size_t)NN * HID;
    float* acc2 = accBase + (size_t)2 * NN * HID;
    float* st0 = statsBase;
    float* st1 = statsBase + 2 * HID;
    float* st2 = statsBase + 4 * HID;

    // init via memset nodes (not kernel launches)
    cudaMemsetAsync(degiPtr, 0, NN * sizeof(int));
    cudaMemsetAsync(cntPtr, 0, NN * sizeof(int));
    cudaMemsetAsync(statsBase, 0, 3 * 2 * HID * sizeof(float));

    k_deg_count<<<(NE + 255) / 256, 256>>>(dst);
    k_scan     <<<1, 1024>>>();
    k_gemm0_scatter<<<GEMM_BLOCKS + SCAT_BLOCKS, 256, MM_SMEM>>>(x, w0, src, dst);
    k_agg      <<<AGG_BLOCKS, 256>>>(b0, acc0, st0);

    k_gemm<HID, true><<<GEMM_BLOCKS, 256, MM_SMEM>>>(acc0, w1, st0, gamma, beta);
    k_agg      <<<AGG_BLOCKS, 256>>>(b1, acc1, st1);

    k_gemm<HID, true><<<GEMM_BLOCKS, 256, MM_SMEM>>>(acc1, w2, st1, gamma, beta);
    k_agg      <<<AGG_BLOCKS, 256>>>(b2, acc2, st2);

    k_att<<<512, 256, SM_FLOATS * (int)sizeof(float)>>>(dp, tp, dn, tn, WD, WT,
                                                        qD, qT, ow, ob,
                                                        gamma, beta, out);
}

// round 17
// speedup vs baseline: 1.1176x; 1.0408x over previous
#include <cuda_runtime.h>
#include <cuda_fp16.h>
#include <math.h>
#include <stdint.h>

#define NN   50000
#define NE   800000
#define IND  256
#define HID  128
#define OUTD 64
#define NB   4096
#define BN_EPS 1e-5f
#define SLOPE  0.01f

// ---------------- scratch (device globals; no allocation allowed) ----------
__device__ int    g_degi[NN];                      // int degree (no self loop)
__device__ int    g_off [NN];                      // CSR offsets (ordered scan)
__device__ int    g_cnt [NN];                      // scatter counters
__device__ int    g_ssrc[NE];                      // src ids sorted by dst
__device__ __half g_s  [(size_t)NN * HID];         // dinv-scaled linear output (fp16)
__device__ float  g_accL[3][(size_t)NN * HID];     // per-layer pre-BN activations
__device__ float  g_stats[3][2 * HID];             // per-layer column sum / sumsq

// ---------------- bf16 helpers ------------------------------------------------
__device__ __forceinline__ uint32_t bf16pair(float f0, float f1) {
    uint32_t r;
    asm("cvt.rn.bf16x2.f32 %0, %1, %2;" : "=r"(r) : "f"(f1), "f"(f0));
    return r;
}
__device__ __forceinline__ float bf_lo(uint32_t p) { return __uint_as_float(p << 16); }
__device__ __forceinline__ float bf_hi(uint32_t p) { return __uint_as_float(p & 0xffff0000u); }

// m16n8k16 row.col bf16 MMA, fp32 accumulate
__device__ __forceinline__ void mma16816(float* c, const uint32_t* a, const uint32_t* b) {
    asm volatile(
        "mma.sync.aligned.m16n8k16.row.col.f32.bf16.bf16.f32 "
        "{%0,%1,%2,%3}, {%4,%5,%6,%7}, {%8,%9}, {%0,%1,%2,%3};"
        : "+f"(c[0]), "+f"(c[1]), "+f"(c[2]), "+f"(c[3])
        : "r"(a[0]), "r"(a[1]), "r"(a[2]), "r"(a[3]), "r"(b[0]), "r"(b[1]));
}

// ---------------- degree / CSR -------------------------------------------------
__global__ void k_deg_count(const int* __restrict__ dst) {
    int e = blockIdx.x * blockDim.x + threadIdx.x;
    if (e < NE) atomicAdd(&g_degi[dst[e]], 1);
}

// Ordered serial scan, coalesced: 1 block, 1024 threads, 49 coalesced tiles.
// Produces bit-identical g_off to the old serial scan, ~10x fewer L1 wavefronts.
__global__ void k_scan() {
    __shared__ int wsum[32];
    __shared__ int carry;
    int t    = threadIdx.x;
    int lane = t & 31;
    int wrp  = t >> 5;
    if (t == 0) carry = 0;
    __syncthreads();

    for (int base = 0; base < NN; base += 1024) {
        int i = base + t;
        int d = (i < NN) ? g_degi[i] : 0;

        // inclusive warp scan (shuffle, no barriers)
        int s = d;
        #pragma unroll
        for (int o = 1; o < 32; o <<= 1) {
            int v = __shfl_up_sync(0xffffffffu, s, o);
            if (lane >= o) s += v;
        }
        if (lane == 31) wsum[wrp] = s;
        __syncthreads();

        // warp 0 scans the 32 warp sums -> exclusive warp offsets
        if (wrp == 0) {
            int ws = wsum[lane];
            int t2 = ws;
            #pragma unroll
            for (int o = 1; o < 32; o <<= 1) {
                int v = __shfl_up_sync(0xffffffffu, t2, o);
                if (lane >= o) t2 += v;
            }
            wsum[lane] = t2 - ws;      // exclusive
        }
        __syncthreads();

        int woff = wsum[wrp];
        int c    = carry;
        if (i < NN) g_off[i] = c + woff + s - d;   // exclusive global offset
        __syncthreads();                            // everyone read carry/wsum
        if (t == 1023) carry = c + woff + s;        // tile total
        __syncthreads();
    }
}

// ---------------- tensor GEMM (split-bf16, mma.sync) --------------------------
// D = Ahi*Bhi + Ahi*Blo + Alo*Bhi ; fp32 accum; epilogue stores fp16 to g_s.
// CTA 128x128, 8 warps (4m x 2n), warp tile 32x64. K chunked at 64.
#define TCH    64
#define TSTR   72
#define TILE_E (128 * TSTR)
#define MM_AHI 0
#define MM_ALO (TILE_E)
#define MM_BHI (2 * TILE_E)
#define MM_BLO (3 * TILE_E)
#define MM_SC  (4 * TILE_E * 2)
#define MM_SMEM (4 * TILE_E * 2 + 2 * HID * 4)

#define GEMM_BLOCKS ((NN + 127) / 128)          // 391
#define SCAT_BLOCKS ((NE + 255) / 256)          // 3125

template <int K, bool BN>
__device__ __forceinline__ void gemm_body(
    int blk,
    const float* __restrict__ X, const float* __restrict__ W,
    const float* __restrict__ stats, const float* __restrict__ gamma,
    const float* __restrict__ beta) {
    extern __shared__ char smc[];
    uint16_t* TB     = (uint16_t*)smc;
    float*    sScale = (float*)(smc + MM_SC);
    float*    sShift = sScale + HID;

    const int t    = threadIdx.x;
    const int wid  = t >> 5;
    const int lane = t & 31;
    const int gid  = lane >> 2;
    const int tig  = lane & 3;
    const int m0   = blk * 128;
    const int wm   = wid & 3;
    const int wn   = wid >> 2;

    if (BN && t < HID) {
        float mean = stats[t] * (1.0f / NN);
        float var  = stats[HID + t] * (1.0f / NN) - mean * mean;
        float sc   = gamma[t] * rsqrtf(var + BN_EPS);
        sScale[t] = sc;
        sShift[t] = beta[t] - mean * sc;
    }
    if (BN) __syncthreads();

    float acc[2][8][4];
    #pragma unroll
    for (int mi = 0; mi < 2; mi++)
        #pragma unroll
        for (int ni = 0; ni < 8; ni++)
            #pragma unroll
            for (int j = 0; j < 4; j++) acc[mi][ni][j] = 0.0f;

    const int NCH = K / TCH;
    for (int kc = 0; kc < NCH; kc++) {
        #pragma unroll
        for (int j = 0; j < 8; j++) {
            int idx = j * 256 + t;
            int row = idx >> 4;
            int c4  = (idx & 15) * 4;
            int m   = m0 + row;
            float4 v = (m < NN)
                ? *(const float4*)(X + (size_t)m * K + kc * TCH + c4)
                : make_float4(0.f, 0.f, 0.f, 0.f);
            if (BN) {
                int kg = kc * TCH + c4;
                v.x = v.x * sScale[kg + 0] + sShift[kg + 0];
                v.y = v.y * sScale[kg + 1] + sShift[kg + 1];
                v.z = v.z * sScale[kg + 2] + sShift[kg + 2];
                v.w = v.w * sScale[kg + 3] + sShift[kg + 3];
            }
            uint32_t hp0 = bf16pair(v.x, v.y);
            uint32_t hp1 = bf16pair(v.z, v.w);
            uint32_t lp0 = bf16pair(v.x - bf_lo(hp0), v.y - bf_hi(hp0));
            uint32_t lp1 = bf16pair(v.z - bf_lo(hp1), v.w - bf_hi(hp1));
            int eo = row * TSTR + c4;
            *(uint2*)(TB + MM_AHI + eo) = make_uint2(hp0, hp1);
            *(uint2*)(TB + MM_ALO + eo) = make_uint2(lp0, lp1);

            float4 w = *(const float4*)(W + (size_t)row * K + kc * TCH + c4);
            uint32_t whp0 = bf16pair(w.x, w.y);
            uint32_t whp1 = bf16pair(w.z, w.w);
            uint32_t wlp0 = bf16pair(w.x - bf_lo(whp0), w.y - bf_hi(whp0));
            uint32_t wlp1 = bf16pair(w.z - bf_lo(whp1), w.w - bf_hi(whp1));
            *(uint2*)(TB + MM_BHI + eo) = make_uint2(whp0, whp1);
            *(uint2*)(TB + MM_BLO + eo) = make_uint2(wlp0, wlp1);
        }
        __syncthreads();

        #pragma unroll
        for (int ks = 0; ks < 4; ks++) {
            const int kb = ks * 16 + 2 * tig;
            uint32_t ahi[2][4], alo[2][4];
            #pragma unroll
            for (int mi = 0; mi < 2; mi++) {
                int r = wm * 32 + mi * 16 + gid;
                ahi[mi][0] = *(const uint32_t*)(TB + MM_AHI + r * TSTR + kb);
                ahi[mi][1] = *(const uint32_t*)(TB + MM_AHI + (r + 8) * TSTR + kb);
                ahi[mi][2] = *(const uint32_t*)(TB + MM_AHI + r * TSTR + kb + 8);
                ahi[mi][3] = *(const uint32_t*)(TB + MM_AHI + (r + 8) * TSTR + kb + 8);
                alo[mi][0] = *(const uint32_t*)(TB + MM_ALO + r * TSTR + kb);
                alo[mi][1] = *(const uint32_t*)(TB + MM_ALO + (r + 8) * TSTR + kb);
                alo[mi][2] = *(const uint32_t*)(TB + MM_ALO + r * TSTR + kb + 8);
                alo[mi][3] = *(const uint32_t*)(TB + MM_ALO + (r + 8) * TSTR + kb + 8);
            }
            #pragma unroll
            for (int ni = 0; ni < 8; ni++) {
                int n = wn * 64 + ni * 8 + gid;
                uint32_t bh[2], bl[2];
                bh[0] = *(const uint32_t*)(TB + MM_BHI + n * TSTR + kb);
                bh[1] = *(const uint32_t*)(TB + MM_BHI + n * TSTR + kb + 8);
                bl[0] = *(const uint32_t*)(TB + MM_BLO + n * TSTR + kb);
                bl[1] = *(const uint32_t*)(TB + MM_BLO + n * TSTR + kb + 8);
                mma16816(acc[0][ni], ahi[0], bh);
                mma16816(acc[1][ni], ahi[1], bh);
                mma16816(acc[0][ni], alo[0], bh);
                mma16816(acc[1][ni], alo[1], bh);
                mma16816(acc[0][ni], ahi[0], bl);
                mma16816(acc[1][ni], ahi[1], bl);
            }
        }
        __syncthreads();
    }

    // epilogue: scale rows by dinv, store fp16 pairs
    __half2* S2 = (__half2*)g_s;               // row stride = 64 half2
    #pragma unroll
    for (int mi = 0; mi < 2; mi++) {
        int r0 = m0 + wm * 32 + mi * 16 + gid;
        int r1 = r0 + 8;
        float d0 = (r0 < NN) ? rsqrtf(1.0f + (float)g_degi[r0]) : 0.0f;
        float d1 = (r1 < NN) ? rsqrtf(1.0f + (float)g_degi[r1]) : 0.0f;
        #pragma unroll
        for (int ni = 0; ni < 8; ni++) {
            int col = wn * 64 + ni * 8 + 2 * tig;     // even
            if (r0 < NN)
                S2[(size_t)r0 * 64 + (col >> 1)] =
                    __floats2half2_rn(acc[mi][ni][0] * d0, acc[mi][ni][1] * d0);
            if (r1 < NN)
                S2[(size_t)r1 * 64 + (col >> 1)] =
                    __floats2half2_rn(acc[mi][ni][2] * d1, acc[mi][ni][3] * d1);
        }
    }
}

// plain GEMM kernel (layers 1, 2)
template <int K, bool BN>
__global__ void __launch_bounds__(256, 2)
k_gemm(const float* __restrict__ X, const float* __restrict__ W,
       const float* __restrict__ stats, const float* __restrict__ gamma,
       const float* __restrict__ beta) {
    gemm_body<K, BN>(blockIdx.x, X, W, stats, gamma, beta);
}

// fused layer-0 GEMM + CSR scatter (independent work, one launch).
__global__ void __launch_bounds__(256, 2)
k_gemm0_scatter(const float* __restrict__ X, const float* __restrict__ W,
                const int* __restrict__ src, const int* __restrict__ dst) {
    if (blockIdx.x >= GEMM_BLOCKS) {
        int e = (blockIdx.x - GEMM_BLOCKS) * 256 + threadIdx.x;
        if (e < NE) {
            int d = dst[e];
            int p = g_off[d] + atomicAdd(&g_cnt[d], 1);
            g_ssrc[p] = src[e];
        }
        return;
    }
    gemm_body<IND, false>(blockIdx.x, X, W, nullptr, nullptr, nullptr);
}

// ---------------- fused CSR aggregation + bias/ReLU + stats ------------------
// fp16 gathers (256B/node row), fp32 accumulation.
__global__ void __launch_bounds__(256)
k_agg(const float* __restrict__ bias, float* __restrict__ outv,
      float* __restrict__ stats) {
    __shared__ float sSum[HID], sSq[HID];
    int t = threadIdx.x;
    if (t < HID) { sSum[t] = 0.0f; sSq[t] = 0.0f; }
    __syncthreads();

    int gw   = (blockIdx.x * 256 + t) >> 5;        // node id
    int lane = t & 31;
    int beg = g_off[gw];
    int end = beg + g_degi[gw];
    const uint2* S = (const uint2*)g_s;            // row stride = 32 uint2 (4 halfs each)

    // self-loop
    float4 acc;
    {
        uint2 p = S[(size_t)gw * 32 + lane];
        float2 a = __half22float2(*(__half2*)&p.x);
        float2 b = __half22float2(*(__half2*)&p.y);
        acc = make_float4(a.x, a.y, b.x, b.y);
    }
    int e = beg;
    for (; e + 4 <= end; e += 4) {
        int u0 = g_ssrc[e], u1 = g_ssrc[e + 1], u2 = g_ssrc[e + 2], u3 = g_ssrc[e + 3];
        uint2 p0 = S[(size_t)u0 * 32 + lane];
        uint2 p1 = S[(size_t)u1 * 32 + lane];
        uint2 p2 = S[(size_t)u2 * 32 + lane];
        uint2 p3 = S[(size_t)u3 * 32 + lane];
        float2 a0 = __half22float2(*(__half2*)&p0.x), b0 = __half22float2(*(__half2*)&p0.y);
        float2 a1 = __half22float2(*(__half2*)&p1.x), b1 = __half22float2(*(__half2*)&p1.y);
        float2 a2 = __half22float2(*(__half2*)&p2.x), b2 = __half22float2(*(__half2*)&p2.y);
        float2 a3 = __half22float2(*(__half2*)&p3.x), b3 = __half22float2(*(__half2*)&p3.y);
        acc.x += (a0.x + a1.x) + (a2.x + a3.x);
        acc.y += (a0.y + a1.y) + (a2.y + a3.y);
        acc.z += (b0.x + b1.x) + (b2.x + b3.x);
        acc.w += (b0.y + b1.y) + (b2.y + b3.y);
    }
    for (; e < end; e++) {
        int u = g_ssrc[e];
        uint2 p = S[(size_t)u * 32 + lane];
        float2 a = __half22float2(*(__half2*)&p.x);
        float2 b = __half22float2(*(__half2*)&p.y);
        acc.x += a.x; acc.y += a.y; acc.z += b.x; acc.w += b.y;
    }

    float dinv = rsqrtf(1.0f + (float)g_degi[gw]);
    float4 b4 = ((const float4*)bias)[lane];
    float4 v;
    v.x = fmaxf(acc.x * dinv + b4.x, 0.0f);
    v.y = fmaxf(acc.y * dinv + b4.y, 0.0f);
    v.z = fmaxf(acc.z * dinv + b4.z, 0.0f);
    v.w = fmaxf(acc.w * dinv + b4.w, 0.0f);
    ((float4*)outv)[(size_t)gw * 32 + lane] = v;

    int c = lane * 4;
    atomicAdd(&sSum[c + 0], v.x);     atomicAdd(&sSq[c + 0], v.x * v.x);
    atomicAdd(&sSum[c + 1], v.y);     atomicAdd(&sSq[c + 1], v.y * v.y);
    atomicAdd(&sSum[c + 2], v.z);     atomicAdd(&sSq[c + 2], v.z * v.z);
    atomicAdd(&sSum[c + 3], v.w);     atomicAdd(&sSq[c + 3], v.w * v.w);
    __syncthreads();

    if (t < 32) {
        float4 s = *(const float4*)&sSum[t * 4];
        atomicAdd((float4*)&stats[t * 4], s);
    } else if (t < 64) {
        int j = t - 32;
        float4 s = *(const float4*)&sSq[j * 4];
        atomicAdd((float4*)&stats[HID + j * 4], s);
    }
}

// ---------------- attention pooling + projection, 32 rows per block ---------
#define SM_W   0
#define SM_E   (SM_W + 128*132)
#define SM_P   (SM_E + 3*128*36)
#define SM_OW  (SM_P + 128*36)
#define SM_ES  (SM_OW + 128*66)
#define SM_AL  (SM_ES + 96)
#define SM_SC  (SM_AL + 96)
#define SM_SH  (SM_SC + 3*128)
#define SM_FLOATS (SM_SH + 3*128)

__global__ void k_att(const int* __restrict__ dp, const int* __restrict__ tp,
                      const int* __restrict__ dn, const int* __restrict__ tn,
                      const float* __restrict__ WD, const float* __restrict__ WT,
                      const float* __restrict__ qD, const float* __restrict__ qT,
                      const float* __restrict__ ow, const float* __restrict__ ob,
                      const float* __restrict__ gamma, const float* __restrict__ beta,
                      float* __restrict__ out) {
    extern __shared__ float sm[];
    __shared__ int s_node[32];

    const int tid = threadIdx.x;           // 256
    const int blk = blockIdx.x;            // 512
    const int grp = blk >> 7;
    const int jb  = (blk & 127) * 32;

    const int*   ids = (grp == 0) ? dp : (grp == 1) ? tp : (grp == 2) ? dn : tn;
    const float* W   = (grp & 1) ? WT : WD;
    const float* q   = (grp & 1) ? qT : qD;

    if (tid < 32) s_node[tid] = ids[jb + tid];
    if (tid < 96) sm[SM_ES + tid] = 0.0f;
    if (tid < 128) {
        #pragma unroll
        for (int l = 0; l < 3; l++) {
            const float* st = g_stats[l];
            float mean = st[tid] * (1.0f / NN);
            float var  = st[HID + tid] * (1.0f / NN) - mean * mean;
            float sc   = gamma[tid] * rsqrtf(var + BN_EPS);
            sm[SM_SC + l * 128 + tid] = sc;
            sm[SM_SH + l * 128 + tid] = beta[tid] - mean * sc;
        }
    }
    __syncthreads();

    #pragma unroll
    for (int i = 0; i < 64; i++) {
        int idx = i * 256 + tid;
        int t = idx >> 7, k = idx & 127;
        sm[SM_W + k * 132 + t] = W[idx];
    }
    #pragma unroll
    for (int i = 0; i < 32; i++) {
        int idx = i * 256 + tid;
        int o = idx >> 7, k = idx & 127;
        sm[SM_OW + k * 66 + o] = ow[idx];
    }
    #pragma unroll
    for (int l = 0; l < 3; l++)
        #pragma unroll
        for (int i = 0; i < 16; i++) {
            int idx = i * 256 + tid;
            int r = idx >> 7, k = idx & 127;
            float raw = g_accL[l][(size_t)s_node[r] * HID + k];
            sm[SM_E + ((l * 128 + k) * 36) + r] =
                raw * sm[SM_SC + l * 128 + k] + sm[SM_SH + l * 128 + k];
        }
    __syncthreads();

    const int tr = tid & 7;
    const int tt = tid >> 3;
    const int r0 = tr * 4;
    const int t0 = tt * 4;

    float ql0 = q[t0], ql1 = q[t0 + 1], ql2 = q[t0 + 2], ql3 = q[t0 + 3];

    for (int l = 0; l < 3; l++) {
        float acc[4][4];
        #pragma unroll
        for (int i = 0; i < 4; i++)
            #pragma unroll
            for (int j = 0; j < 4; j++) acc[i][j] = 0.0f;

        const float* eb = sm + SM_E + (l * 128) * 36;
        #pragma unroll 4
        for (int k = 0; k < 128; k++) {
            float4 a = *(const float4*)(eb + k * 36 + r0);
            float4 b = *(const float4*)(sm + SM_W + k * 132 + t0);
            acc[0][0] += a.x * b.x; acc[0][1] += a.x * b.y; acc[0][2] += a.x * b.z; acc[0][3] += a.x * b.w;
            acc[1][0] += a.y * b.x; acc[1][1] += a.y * b.y; acc[1][2] += a.y * b.z; acc[1][3] += a.y * b.w;
            acc[2][0] += a.z * b.x; acc[2][1] += a.z * b.y; acc[2][2] += a.z * b.z; acc[2][3] += a.z * b.w;
            acc[3][0] += a.w * b.x; acc[3][1] += a.w * b.y; acc[3][2] += a.w * b.z; acc[3][3] += a.w * b.w;
        }
        #pragma unroll
        for (int i = 0; i < 4; i++) {
            float h0 = acc[i][0], h1 = acc[i][1], h2 = acc[i][2], h3 = acc[i][3];
            h0 = (h0 > 0.0f) ? h0 : SLOPE * h0;
            h1 = (h1 > 0.0f) ? h1 : SLOPE * h1;
            h2 = (h2 > 0.0f) ? h2 : SLOPE * h2;
            h3 = (h3 > 0.0f) ? h3 : SLOPE * h3;
            float pe = h0 * ql0 + h1 * ql1 + h2 * ql2 + h3 * ql3;
            atomicAdd(&sm[SM_ES + l * 32 + r0 + i], pe);
        }
    }
    __syncthreads();

    if (tid < 32) {
        float e0 = sm[SM_ES + tid], e1 = sm[SM_ES + 32 + tid], e2 = sm[SM_ES + 64 + tid];
        float m  = fmaxf(e0, fmaxf(e1, e2));
        float a0 = expf(e0 - m), a1 = expf(e1 - m), a2 = expf(e2 - m);
        float s  = 1.0f / (a0 + a1 + a2);
        sm[SM_AL + tid]      = a0 * s;
        sm[SM_AL + 32 + tid] = a1 * s;
        sm[SM_AL + 64 + tid] = a2 * s;
    }
    __syncthreads();

    #pragma unroll
    for (int i = 0; i < 16; i++) {
        int idx = i * 256 + tid;
        int k = idx >> 5, r = idx & 31;
        float v = sm[SM_AL + r]      * sm[SM_E + (0 * 128 + k) * 36 + r]
                + sm[SM_AL + 32 + r] * sm[SM_E + (1 * 128 + k) * 36 + r]
                + sm[SM_AL + 64 + r] * sm[SM_E + (2 * 128 + k) * 36 + r];
        sm[SM_P + k * 36 + r] = v;
    }
    __syncthreads();

    {
        const int o0 = tt * 2;
        float a0 = 0, a1 = 0, b0 = 0, b1 = 0, c0 = 0, c1 = 0, d0 = 0, d1 = 0;
        #pragma unroll 4
        for (int k = 0; k < 128; k++) {
            float4 p = *(const float4*)(sm + SM_P + k * 36 + r0);
            float2 w2 = *(const float2*)(sm + SM_OW + k * 66 + o0);
            a0 += p.x * w2.x; a1 += p.x * w2.y;
            b0 += p.y * w2.x; b1 += p.y * w2.y;
            c0 += p.z * w2.x; c1 += p.z * w2.y;
            d0 += p.w * w2.x; d1 += p.w * w2.y;
        }
        float ob0 = ob[o0], ob1 = ob[o0 + 1];
        int row = blk * 32 + r0;
        out[(size_t)(row + 0) * OUTD + o0]     = a0 + ob0;
        out[(size_t)(row + 0) * OUTD + o0 + 1] = a1 + ob1;
        out[(size_t)(row + 1) * OUTD + o0]     = b0 + ob0;
        out[(size_t)(row + 1) * OUTD + o0 + 1] = b1 + ob1;
        out[(size_t)(row + 2) * OUTD + o0]     = c0 + ob0;
        out[(size_t)(row + 2) * OUTD + o0 + 1] = c1 + ob1;
        out[(size_t)(row + 3) * OUTD + o0]     = d0 + ob0;
        out[(size_t)(row + 3) * OUTD + o0 + 1] = d1 + ob1;
    }
}

// ---------------- launch -----------------------------------------------------
extern "C" void kernel_launch(void* const* d_in, const int* in_sizes, int n_in,
                              void* d_out, int out_size) {
    const float* x     = (const float*)d_in[0];
    const int*   ei    = (const int*)  d_in[1];
    const int*   dp    = (const int*)  d_in[2];
    const int*   tp    = (const int*)  d_in[3];
    const int*   dn    = (const int*)  d_in[4];
    const int*   tn    = (const int*)  d_in[5];
    const float* w0    = (const float*)d_in[7];
    const float* b0    = (const float*)d_in[8];
    const float* w1    = (const float*)d_in[9];
    const float* b1    = (const float*)d_in[10];
    const float* w2    = (const float*)d_in[11];
    const float* b2    = (const float*)d_in[12];
    const float* gamma = (const float*)d_in[13];
    const float* beta  = (const float*)d_in[14];
    const float* WD    = (const float*)d_in[15];
    const float* WT    = (const float*)d_in[16];
    const float* qD    = (const float*)d_in[17];
    const float* qT    = (const float*)d_in[18];
    const float* ow    = (const float*)d_in[19];
    const float* ob    = (const float*)d_in[20];
    float*       out   = (float*)d_out;

    const int* src = ei;
    const int* dst = ei + NE;

    float* accBase = nullptr;
    cudaGetSymbolAddress((void**)&accBase, g_accL);
    float* statsBase = nullptr;
    cudaGetSymbolAddress((void**)&statsBase, g_stats);
    int* degiPtr = nullptr;
    cudaGetSymbolAddress((void**)&degiPtr, g_degi);
    int* cntPtr = nullptr;
    cudaGetSymbolAddress((void**)&cntPtr, g_cnt);

    static bool attr_done = false;
    if (!attr_done) {
        cudaFuncSetAttribute(k_att, cudaFuncAttributeMaxDynamicSharedMemorySize,
                             SM_FLOATS * (int)sizeof(float));
        cudaFuncSetAttribute(k_gemm0_scatter,
                             cudaFuncAttributeMaxDynamicSharedMemorySize, MM_SMEM);
        cudaFuncSetAttribute(k_gemm<HID, true>,
                             cudaFuncAttributeMaxDynamicSharedMemorySize, MM_SMEM);
        attr_done = true;
    }

    const int AGG_BLOCKS = NN / 8;                  // 6250 (exact)

    float* acc0 = accBase;
    float* acc1 = accBase + (size_t)NN * HID;
    float* acc2 = accBase + (size_t)2 * NN * HID;
    float* st0 = statsBase;
    float* st1 = statsBase + 2 * HID;
    float* st2 = statsBase + 4 * HID;

    // init via memset nodes (not kernel launches)
    cudaMemsetAsync(degiPtr, 0, NN * sizeof(int));
    cudaMemsetAsync(cntPtr, 0, NN * sizeof(int));
    cudaMemsetAsync(statsBase, 0, 3 * 2 * HID * sizeof(float));

    k_deg_count<<<(NE + 255) / 256, 256>>>(dst);
    k_scan     <<<1, 1024>>>();
    k_gemm0_scatter<<<GEMM_BLOCKS + SCAT_BLOCKS, 256, MM_SMEM>>>(x, w0, src, dst);
    k_agg      <<<AGG_BLOCKS, 256>>>(b0, acc0, st0);

    k_gemm<HID, true><<<GEMM_BLOCKS, 256, MM_SMEM>>>(acc0, w1, st0, gamma, beta);
    k_agg      <<<AGG_BLOCKS, 256>>>(b1, acc1, st1);

    k_gemm<HID, true><<<GEMM_BLOCKS, 256, MM_SMEM>>>(acc1, w2, st1, gamma, beta);
    k_agg      <<<AGG_BLOCKS, 256>>>(b2, acc2, st2);

    k_att<<<512, 256, SM_FLOATS * (int)sizeof(float)>>>(dp, tp, dn, tn, WD, WT,
                                                        qD, qT, ow, ob,
                                                        gamma, beta, out);
}